// round 1
// baseline (speedup 1.0000x reference)
#include <cuda_runtime.h>
#include <math.h>

// Problem constants
#define BB 512
#define HH 512
#define EE 300
#define LCC 100
#define OO 2004
#define ATTN_IN 52524      // H*(LC+2)+E
#define GRU_IN 1324        // 2H+E
#define MLP_IN 1836        // 3H+E
#define ANNOT_K 51200      // LC*H
#define NSPLIT 64
#define KCHUNK 800         // 51200/64

// ---- scratch (device globals; no allocation allowed) ----
#define OFF_AHEAD 0                     // 512*1324 = [h0|emb|ans]
#define OFF_MINP  677888                // 512*1836 = [h_new|c_t|ans|emb]
#define OFF_PART  1617920               // 64*512*100
#define OFF_LOG   4894720               // 512*100
#define OFF_ATTNW 4945920               // 512*100
#define OFF_GI    4997120               // 512*1536
#define OFF_GH    5783552               // 512*1536
#define OFF_ET    6569984               // 512*512
#define OFF_OLOG  6832128               // 512*2004
#define OFF_Z1    7858176               // 512*1024
#define OFF_Z2    8382464               // 512*512
#define SCRATCH_TOTAL 8644608

__device__ float g_scratch[SCRATCH_TOTAL];

// ---------------- reductions ----------------
__device__ __forceinline__ float warpReduceSum(float v) {
    #pragma unroll
    for (int o = 16; o > 0; o >>= 1) v += __shfl_xor_sync(0xffffffffu, v, o);
    return v;
}
__device__ __forceinline__ float warpReduceMax(float v) {
    #pragma unroll
    for (int o = 16; o > 0; o >>= 1) v = fmaxf(v, __shfl_xor_sync(0xffffffffu, v, o));
    return v;
}

// ---------------- K1: embedding + concat builders ----------------
// ahead[b] = [h0(512) | emb(300) | ans(512)]
// minp[b]  = [h_new(512, later) | c_t(512, later) | ans(512) | emb(300)]
__global__ void embed_kernel(const int* __restrict__ input,
                             const int* __restrict__ input_d,
                             const float* __restrict__ hidden,
                             const float* __restrict__ ans,
                             const float* __restrict__ emb_w,
                             const float* __restrict__ emb_d_w,
                             float* __restrict__ ahead,
                             float* __restrict__ minp)
{
    int b = blockIdx.x;
    int t = threadIdx.x;  // 128
    int tok = input[b];
    const float* src;
    if (tok > 2003) {
        int di = tok - 2004;
        if (di > LCC - 1) di = LCC - 1;
        if (di < 0) di = 0;
        int dt = input_d[b * LCC + di];
        src = emb_d_w + (size_t)dt * EE;
    } else {
        int tv = tok < 0 ? 0 : tok;
        src = emb_w + (size_t)tv * EE;
    }
    float* ah = ahead + (size_t)b * GRU_IN;
    float* mp = minp + (size_t)b * MLP_IN;
    for (int j = t; j < EE; j += 128) {
        float e = src[j];
        ah[512 + j] = e;
        mp[1536 + j] = e;
    }
    for (int h = t; h < HH; h += 128) {
        float hv = hidden[(size_t)b * HH + h];
        float av = ans[(size_t)b * HH + h];
        ah[h] = hv;
        ah[812 + h] = av;
        mp[1024 + h] = av;
    }
}

// ---------------- K2: split-K GEMM for the annot part of attention ----------------
// partial[z][m][n] = annot(512,51200)[:, z*800:(z+1)*800] @ Wannot(100,51200)^T chunk
__global__ void __launch_bounds__(256) sgemm_attn(const float* __restrict__ A,
                                                  const float* __restrict__ Bw,
                                                  float* __restrict__ partial)
{
    __shared__ float As[16][128];
    __shared__ float Bs[16][128];
    const int t = threadIdx.x;
    const int tx = t & 15, ty = t >> 4;
    const int m0 = blockIdx.x << 7;
    const int kbeg = blockIdx.z * KCHUNK;
    const int lrow = t >> 2;          // 0..63
    const int lcol = (t & 3) << 2;    // 0,4,8,12

    const float* Ap0 = A + (size_t)(m0 + lrow) * ANNOT_K + lcol;
    const float* Ap1 = Ap0 + (size_t)64 * ANNOT_K;
    const float* Bp0 = Bw + (size_t)lrow * ATTN_IN + lcol;
    const int n1 = lrow + 64;
    const float* Bp1 = Bw + (size_t)(n1 < LCC ? n1 : 0) * ATTN_IN + lcol;
    const bool b1v = (n1 < LCC);

    float acc[8][8];
    #pragma unroll
    for (int i = 0; i < 8; i++)
        #pragma unroll
        for (int j = 0; j < 8; j++) acc[i][j] = 0.f;

    for (int k0 = kbeg; k0 < kbeg + KCHUNK; k0 += 16) {
        float4 a0 = *reinterpret_cast<const float4*>(Ap0 + k0);
        float4 a1 = *reinterpret_cast<const float4*>(Ap1 + k0);
        float4 b0 = *reinterpret_cast<const float4*>(Bp0 + k0);
        float4 b1 = b1v ? *reinterpret_cast<const float4*>(Bp1 + k0)
                        : make_float4(0.f, 0.f, 0.f, 0.f);
        As[lcol + 0][lrow] = a0.x; As[lcol + 1][lrow] = a0.y;
        As[lcol + 2][lrow] = a0.z; As[lcol + 3][lrow] = a0.w;
        As[lcol + 0][lrow + 64] = a1.x; As[lcol + 1][lrow + 64] = a1.y;
        As[lcol + 2][lrow + 64] = a1.z; As[lcol + 3][lrow + 64] = a1.w;
        Bs[lcol + 0][lrow] = b0.x; Bs[lcol + 1][lrow] = b0.y;
        Bs[lcol + 2][lrow] = b0.z; Bs[lcol + 3][lrow] = b0.w;
        Bs[lcol + 0][lrow + 64] = b1.x; Bs[lcol + 1][lrow + 64] = b1.y;
        Bs[lcol + 2][lrow + 64] = b1.z; Bs[lcol + 3][lrow + 64] = b1.w;
        __syncthreads();
        #pragma unroll
        for (int kk = 0; kk < 16; kk++) {
            float4 x0 = *reinterpret_cast<const float4*>(&As[kk][ty << 2]);
            float4 x1 = *reinterpret_cast<const float4*>(&As[kk][64 + (ty << 2)]);
            float4 y0 = *reinterpret_cast<const float4*>(&Bs[kk][tx << 2]);
            float4 y1 = *reinterpret_cast<const float4*>(&Bs[kk][64 + (tx << 2)]);
            float am[8] = {x0.x, x0.y, x0.z, x0.w, x1.x, x1.y, x1.z, x1.w};
            float bn[8] = {y0.x, y0.y, y0.z, y0.w, y1.x, y1.y, y1.z, y1.w};
            #pragma unroll
            for (int i = 0; i < 8; i++)
                #pragma unroll
                for (int j = 0; j < 8; j++)
                    acc[i][j] = fmaf(am[i], bn[j], acc[i][j]);
        }
        __syncthreads();
    }

    float* P = partial + (size_t)blockIdx.z * BB * LCC;
    #pragma unroll
    for (int i = 0; i < 8; i++) {
        int m = m0 + ((i < 4) ? ((ty << 2) + i) : (64 + (ty << 2) + i - 4));
        #pragma unroll
        for (int j = 0; j < 8; j++) {
            int n = (j < 4) ? ((tx << 2) + j) : (64 + (tx << 2) + j - 4);
            if (n < LCC) P[(size_t)m * LCC + n] = acc[i][j];
        }
    }
}

// ---------------- generic 64x64x16 fp32 GEMM: C = A @ B^T (+bias)(+tanh) ----------------
// M assumed multiple of 64 (always 512 here). N,K arbitrary (K multiple of 4).
template <int ACT>
__global__ void __launch_bounds__(256) sgemm64(int N, int K,
                                               const float* __restrict__ A, int lda,
                                               const float* __restrict__ B, int ldb,
                                               const float* __restrict__ bias,
                                               float* __restrict__ C, int ldc)
{
    __shared__ float As[16][64];
    __shared__ float Bs[16][64];
    const int t = threadIdx.x;
    const int tx = t & 15, ty = t >> 4;
    const int m0 = blockIdx.x << 6;
    const int n0 = blockIdx.y << 6;
    const int lrow = t >> 2;
    const int lcol = (t & 3) << 2;

    const float* Ap = A + (size_t)(m0 + lrow) * lda;
    const int nrow = n0 + lrow;
    const float* Bp = B + (size_t)(nrow < N ? nrow : 0) * ldb;
    const bool bv = (nrow < N);

    float acc[4][4];
    #pragma unroll
    for (int i = 0; i < 4; i++)
        #pragma unroll
        for (int j = 0; j < 4; j++) acc[i][j] = 0.f;

    for (int k0 = 0; k0 < K; k0 += 16) {
        float4 av = make_float4(0.f, 0.f, 0.f, 0.f);
        float4 bw = make_float4(0.f, 0.f, 0.f, 0.f);
        if (k0 + lcol < K) {   // K % 4 == 0 so float4 is all-or-nothing
            av = *reinterpret_cast<const float4*>(Ap + k0 + lcol);
            if (bv) bw = *reinterpret_cast<const float4*>(Bp + k0 + lcol);
        }
        As[lcol + 0][lrow] = av.x; As[lcol + 1][lrow] = av.y;
        As[lcol + 2][lrow] = av.z; As[lcol + 3][lrow] = av.w;
        Bs[lcol + 0][lrow] = bw.x; Bs[lcol + 1][lrow] = bw.y;
        Bs[lcol + 2][lrow] = bw.z; Bs[lcol + 3][lrow] = bw.w;
        __syncthreads();
        #pragma unroll
        for (int kk = 0; kk < 16; kk++) {
            float4 a = *reinterpret_cast<const float4*>(&As[kk][ty << 2]);
            float4 bq = *reinterpret_cast<const float4*>(&Bs[kk][tx << 2]);
            float am[4] = {a.x, a.y, a.z, a.w};
            float bn[4] = {bq.x, bq.y, bq.z, bq.w};
            #pragma unroll
            for (int i = 0; i < 4; i++)
                #pragma unroll
                for (int j = 0; j < 4; j++)
                    acc[i][j] = fmaf(am[i], bn[j], acc[i][j]);
        }
        __syncthreads();
    }

    #pragma unroll
    for (int i = 0; i < 4; i++) {
        int m = m0 + (ty << 2) + i;
        #pragma unroll
        for (int j = 0; j < 4; j++) {
            int n = n0 + (tx << 2) + j;
            if (n < N) {
                float v = acc[i][j] + (bias ? bias[n] : 0.f);
                if (ACT == 1) v = tanhf(v);
                C[(size_t)m * ldc + n] = v;
            }
        }
    }
}

// ---------------- K3: reduce split-K partials + head logits, tanh, softmax ----------------
__global__ void attn_finalize(const float* __restrict__ logits0,
                              const float* __restrict__ partial,
                              float* __restrict__ attnw)
{
    int b = blockIdx.x, t = threadIdx.x;  // 128 threads
    __shared__ float sred[4];
    float v = -1e30f;
    if (t < LCC) {
        float acc = logits0[(size_t)b * LCC + t];
        #pragma unroll 4
        for (int s = 0; s < NSPLIT; s++)
            acc += partial[((size_t)s * BB + b) * LCC + t];
        v = tanhf(acc);
    }
    float m = warpReduceMax(v);
    if ((t & 31) == 0) sred[t >> 5] = m;
    __syncthreads();
    m = fmaxf(fmaxf(sred[0], sred[1]), fmaxf(sred[2], sred[3]));
    float e = (t < LCC) ? expf(v - m) : 0.f;
    float ss = warpReduceSum(e);
    __syncthreads();
    if ((t & 31) == 0) sred[t >> 5] = ss;
    __syncthreads();
    float tot = sred[0] + sred[1] + sred[2] + sred[3];
    if (t < LCC) attnw[(size_t)b * LCC + t] = e / tot;
}

// ---------------- K4: c_t = einsum('bl,blh->bh') ----------------
__global__ void ct_kernel(const float* __restrict__ annot,
                          const float* __restrict__ attnw,
                          float* __restrict__ minp)
{
    int b = blockIdx.x, t = threadIdx.x;  // 128
    __shared__ float w[LCC];
    if (t < LCC) w[t] = attnw[(size_t)b * LCC + t];
    __syncthreads();
    const float* Ab = annot + (size_t)b * ANNOT_K;
    for (int h = t; h < HH; h += 128) {
        float acc = 0.f;
        #pragma unroll 4
        for (int l = 0; l < LCC; l++) acc = fmaf(w[l], Ab[l * HH + h], acc);
        minp[(size_t)b * MLP_IN + 512 + h] = acc;
    }
}

// ---------------- K5: GRU elementwise ----------------
__global__ void gru_kernel(const float* __restrict__ gi,
                           const float* __restrict__ gh,
                           const float* __restrict__ h0,
                           float* __restrict__ minp,
                           float* __restrict__ out0,
                           float* __restrict__ out1)
{
    int i = blockIdx.x * blockDim.x + threadIdx.x;  // 512*512
    int b = i >> 9, h = i & 511;
    const float* gib = gi + (size_t)b * 1536;
    const float* ghb = gh + (size_t)b * 1536;
    float r = 1.f / (1.f + expf(-(gib[h] + ghb[h])));
    float z = 1.f / (1.f + expf(-(gib[512 + h] + ghb[512 + h])));
    float n = tanhf(gib[1024 + h] + r * ghb[1024 + h]);
    float hn = (1.f - z) * n + z * h0[i];
    minp[(size_t)b * MLP_IN + h] = hn;
    out0[i] = hn;
    out1[i] = hn;
}

// ---------------- K6: z_t + output softmax + log, write p_t ----------------
__global__ void final_kernel(const float* __restrict__ olog,
                             const float* __restrict__ z2,
                             const float* __restrict__ zt_W3,
                             const float* __restrict__ zt_b3,
                             const float* __restrict__ attnw,
                             float* __restrict__ pout)
{
    int b = blockIdx.x, t = threadIdx.x;  // 256 threads, 8 warps
    __shared__ float sred[8];
    __shared__ float sbc;

    // z_t = sigmoid(z2[b] . zt_W3 + zt_b3)
    float s = 0.f;
    for (int h = t; h < HH; h += 256) s = fmaf(z2[(size_t)b * HH + h], zt_W3[h], s);
    s = warpReduceSum(s);
    if ((t & 31) == 0) sred[t >> 5] = s;
    __syncthreads();
    if (t == 0) {
        float tot = 0.f;
        for (int w = 0; w < 8; w++) tot += sred[w];
        sbc = 1.f / (1.f + expf(-(tot + zt_b3[0])));
    }
    __syncthreads();
    float zt = sbc;

    const float* ob = olog + (size_t)b * OO;
    float mx = -1e30f;
    for (int j = t; j < OO; j += 256) mx = fmaxf(mx, ob[j]);
    mx = warpReduceMax(mx);
    __syncthreads();  // all threads have consumed sbc (zt)
    if ((t & 31) == 0) sred[t >> 5] = mx;
    __syncthreads();
    if (t == 0) {
        float mm = sred[0];
        for (int w = 1; w < 8; w++) mm = fmaxf(mm, sred[w]);
        sbc = mm;
    }
    __syncthreads();
    mx = sbc;

    float se = 0.f;
    for (int j = t; j < OO; j += 256) se += expf(ob[j] - mx);
    se = warpReduceSum(se);
    __syncthreads();
    if ((t & 31) == 0) sred[t >> 5] = se;
    __syncthreads();
    if (t == 0) {
        float tot = 0.f;
        for (int w = 0; w < 8; w++) tot += sred[w];
        sbc = tot;
    }
    __syncthreads();
    float inv = 1.f / sbc;

    float* pb = pout + (size_t)b * (OO + LCC);
    for (int j = t; j < OO; j += 256)
        pb[j] = logf(expf(ob[j] - mx) * inv * zt + 1e-20f);
    float omz = 1.f - zt;
    for (int l = t; l < LCC; l += 256)
        pb[OO + l] = logf(attnw[(size_t)b * LCC + l] * omz + 1e-20f);
}

// ---------------- launch ----------------
extern "C" void kernel_launch(void* const* d_in, const int* in_sizes, int n_in,
                              void* d_out, int out_size)
{
    const int*   input   = (const int*)d_in[0];
    const int*   input_d = (const int*)d_in[1];
    const float* hidden  = (const float*)d_in[2];
    const float* annot   = (const float*)d_in[3];
    const float* ans     = (const float*)d_in[4];
    const float* emb_w   = (const float*)d_in[5];
    const float* emb_d_w = (const float*)d_in[6];
    const float* attn_W  = (const float*)d_in[7];
    const float* attn_b  = (const float*)d_in[8];
    const float* W_ih    = (const float*)d_in[9];
    const float* W_hh    = (const float*)d_in[10];
    const float* b_ih    = (const float*)d_in[11];
    const float* b_hh    = (const float*)d_in[12];
    const float* mlp_W   = (const float*)d_in[13];
    const float* mlp_b   = (const float*)d_in[14];
    const float* out_W   = (const float*)d_in[15];
    const float* out_b   = (const float*)d_in[16];
    const float* zt_W1   = (const float*)d_in[17];
    const float* zt_b1   = (const float*)d_in[18];
    const float* zt_W2   = (const float*)d_in[19];
    const float* zt_b2   = (const float*)d_in[20];
    const float* zt_W3   = (const float*)d_in[21];
    const float* zt_b3   = (const float*)d_in[22];
    float* out = (float*)d_out;

    float* scr = nullptr;
    cudaGetSymbolAddress((void**)&scr, g_scratch);
    float* ahead = scr + OFF_AHEAD;
    float* minp  = scr + OFF_MINP;
    float* part  = scr + OFF_PART;
    float* logi  = scr + OFF_LOG;
    float* attnw = scr + OFF_ATTNW;
    float* gi    = scr + OFF_GI;
    float* gh    = scr + OFF_GH;
    float* et    = scr + OFF_ET;
    float* ologs = scr + OFF_OLOG;
    float* z1    = scr + OFF_Z1;
    float* z2    = scr + OFF_Z2;

    // 1. embedding + concat staging
    embed_kernel<<<BB, 128>>>(input, input_d, hidden, ans, emb_w, emb_d_w, ahead, minp);
    // 2. attention: annot part (split-K) + head part, then finalize
    sgemm_attn<<<dim3(4, 1, NSPLIT), 256>>>(annot, attn_W + 1324, part);
    sgemm64<0><<<dim3(8, 2), 256>>>(LCC, GRU_IN, ahead, GRU_IN, attn_W, ATTN_IN, attn_b, logi, LCC);
    attn_finalize<<<BB, 128>>>(logi, part, attnw);
    // 3. context vector
    ct_kernel<<<BB, 128>>>(annot, attnw, minp);
    // 4. GRU
    sgemm64<0><<<dim3(8, 24), 256>>>(1536, GRU_IN, minp + 512, MLP_IN, W_ih, GRU_IN, b_ih, gi, 1536);
    sgemm64<0><<<dim3(8, 24), 256>>>(1536, HH, hidden, HH, W_hh, HH, b_hh, gh, 1536);
    gru_kernel<<<1024, 256>>>(gi, gh, hidden, minp, out, out + BB * HH);
    // 5. mlp + output head
    sgemm64<0><<<dim3(8, 8), 256>>>(HH, MLP_IN, minp, MLP_IN, mlp_W, MLP_IN, mlp_b, et, HH);
    sgemm64<0><<<dim3(8, 32), 256>>>(OO, HH, et, HH, out_W, HH, out_b, ologs, OO);
    // 6. z gate
    sgemm64<1><<<dim3(8, 16), 256>>>(1024, MLP_IN, minp, MLP_IN, zt_W1, MLP_IN, zt_b1, z1, 1024);
    sgemm64<1><<<dim3(8, 8), 256>>>(HH, 1024, z1, 1024, zt_W2, 1024, zt_b2, z2, HH);
    // 7. final softmax/log + p_t
    final_kernel<<<BB, 256>>>(ologs, z2, zt_W3, zt_b3, attnw, out + 2 * BB * HH);
}

// round 3
// speedup vs baseline: 2.8842x; 2.8842x over previous
#include <cuda_runtime.h>
#include <cstdint>
#include <math.h>

// ---------------- problem constants ----------------
#define BB 512
#define HH 512
#define EE 300
#define LCC 100
#define OO 2004
#define ATTN_IN 52524      // H*(LC+2)+E
#define GRU_IN 1324        // 2H+E
#define MLP_IN 1836        // 3H+E
#define ANNOT_K 51200      // LC*H
#define NSPLIT 72          // 64 annot splits + 8 head splits

// ---------------- scratch (device globals) ----------------
#define OFF_AHEAD 0                     // 512*1324
#define OFF_MINP  677888                // 512*1836
#define OFF_PART  1617920               // 72*512*100
#define OFF_ATTNW 5304320               // 512*100
#define OFF_GIP   5355520               // 2*512*1536
#define OFF_GHP   6928384               // 2*512*1536
#define OFF_ETP   8501248               // 2*512*512
#define OFF_ET    9025536               // 512*512
#define OFF_OLOG  9287680               // 512*2004
#define OFF_Z1P   10313728              // 2*512*1024
#define OFF_Z1    11362304              // 512*1024
#define OFF_Z2P   11886592              // 2*512*512
#define OFF_Z2    12410880              // 512*512
#define SCRATCH_TOTAL 12673024

__device__ float g_scratch[SCRATCH_TOTAL];

// ---------------- helpers ----------------
__device__ __forceinline__ uint32_t f2t(float f) {
    uint32_t u;
    asm("cvt.rna.tf32.f32 %0, %1;" : "=r"(u) : "f"(f));
    return u;
}
__device__ __forceinline__ void mma_tf32(float* c, const uint32_t* a, const uint32_t* b) {
    asm volatile(
        "mma.sync.aligned.m16n8k8.row.col.f32.tf32.tf32.f32 "
        "{%0,%1,%2,%3}, {%4,%5,%6,%7}, {%8,%9}, {%0,%1,%2,%3};"
        : "+f"(c[0]), "+f"(c[1]), "+f"(c[2]), "+f"(c[3])
        : "r"(a[0]), "r"(a[1]), "r"(a[2]), "r"(a[3]), "r"(b[0]), "r"(b[1]));
}
__device__ __forceinline__ float warpReduceSum(float v) {
    #pragma unroll
    for (int o = 16; o > 0; o >>= 1) v += __shfl_xor_sync(0xffffffffu, v, o);
    return v;
}
__device__ __forceinline__ float warpReduceMax(float v) {
    #pragma unroll
    for (int o = 16; o > 0; o >>= 1) v = fmaxf(v, __shfl_xor_sync(0xffffffffu, v, o));
    return v;
}

// ================= tf32 mma.sync GEMM: C = A(M,K) @ B(N,K)^T =================
// BM=64, BN=128, BK=32. 256 threads = 8 warps (2m x 4n), warp tile 32x32.
// Split-K via blockIdx.z: C slice z at C + z*512*ldc, K range [z*KC, z*KC+KC).
// XOR swizzle (word col ^= (row&7)<<2) -> conflict-free STS.128 and LDS.32.
#define BM 64
#define BN 128
#define BK 32
#define AW (BM * BK)        // 2048 words
#define BW (BN * BK)        // 4096 words
#define TMMA_SMEM ((2 * (AW + BW)) * 4)  // 49152 B

__global__ void __launch_bounds__(256) tmma(
    int N, int K, int KC,
    const float* __restrict__ A, int lda,
    const float* __restrict__ B, int ldb,
    const float* __restrict__ bias,
    float* __restrict__ C, int ldc)
{
    extern __shared__ uint32_t sm[];
    uint32_t* sA = sm;             // 2 * AW
    uint32_t* sB = sm + 2 * AW;    // 2 * BW

    const int tid = threadIdx.x;
    const int lane = tid & 31, wid = tid >> 5;
    const int wm = wid & 1, wn = wid >> 1;
    const int gid = lane >> 2, tg = lane & 3;

    const int m0 = blockIdx.x * BM;
    const int n0 = blockIdx.y * BN;
    const int kstart = blockIdx.z * KC;
    int kend = kstart + KC; if (kend > K) kend = K;
    const int nb = (kend - kstart + BK - 1) / BK;

    const int lr = tid >> 3;           // 0..31
    const int lc = (tid & 7) << 2;     // 0,4,..,28

    float c[2][4][4];
    #pragma unroll
    for (int i = 0; i < 2; i++)
        #pragma unroll
        for (int j = 0; j < 4; j++)
            #pragma unroll
            for (int q = 0; q < 4; q++) c[i][j][q] = 0.f;

    const float4 z4 = make_float4(0.f, 0.f, 0.f, 0.f);
    float4 av[2], bv[4];

    // ---- prologue gmem load (k-block 0) ----
    {
        int kk = kstart + lc;
        bool kv = kk < kend;
        #pragma unroll
        for (int i = 0; i < 2; i++) {
            int m = m0 + lr + i * 32;
            av[i] = kv ? *(const float4*)(A + (size_t)m * lda + kk) : z4;
        }
        #pragma unroll
        for (int i = 0; i < 4; i++) {
            int n = n0 + lr + i * 32;
            bv[i] = (kv && n < N) ? *(const float4*)(B + (size_t)n * ldb + kk) : z4;
        }
    }
    // store buffer 0
    {
        uint32_t* dA = sA;
        uint32_t* dB = sB;
        #pragma unroll
        for (int i = 0; i < 2; i++) {
            int r = lr + i * 32;
            int w = r * BK + (lc ^ ((r & 7) << 2));
            *(uint4*)(dA + w) = make_uint4(f2t(av[i].x), f2t(av[i].y), f2t(av[i].z), f2t(av[i].w));
        }
        #pragma unroll
        for (int i = 0; i < 4; i++) {
            int r = lr + i * 32;
            int w = r * BK + (lc ^ ((r & 7) << 2));
            *(uint4*)(dB + w) = make_uint4(f2t(bv[i].x), f2t(bv[i].y), f2t(bv[i].z), f2t(bv[i].w));
        }
    }
    __syncthreads();

    for (int kb = 0; kb < nb; kb++) {
        const int p = kb & 1;
        const bool has_next = (kb + 1 < nb);
        // prefetch next k-block into regs (covers DRAM latency under the mma work)
        if (has_next) {
            int kk = kstart + (kb + 1) * BK + lc;
            bool kv = kk < kend;
            #pragma unroll
            for (int i = 0; i < 2; i++) {
                int m = m0 + lr + i * 32;
                av[i] = kv ? *(const float4*)(A + (size_t)m * lda + kk) : z4;
            }
            #pragma unroll
            for (int i = 0; i < 4; i++) {
                int n = n0 + lr + i * 32;
                bv[i] = (kv && n < N) ? *(const float4*)(B + (size_t)n * ldb + kk) : z4;
            }
        }
        // compute on buffer p
        const uint32_t* bufA = sA + p * AW;
        const uint32_t* bufB = sB + p * BW;
        #pragma unroll
        for (int ks = 0; ks < 4; ks++) {
            const int k0 = ks * 8;
            uint32_t af[2][4], bf[4][2];
            #pragma unroll
            for (int mt = 0; mt < 2; mt++) {
                int r0 = wm * 32 + mt * 16 + gid;
                int r1 = r0 + 8;
                int s = (r0 & 7) << 2;   // (r1&7)==(r0&7)
                af[mt][0] = bufA[r0 * BK + ((k0 + tg) ^ s)];
                af[mt][1] = bufA[r1 * BK + ((k0 + tg) ^ s)];
                af[mt][2] = bufA[r0 * BK + ((k0 + tg + 4) ^ s)];
                af[mt][3] = bufA[r1 * BK + ((k0 + tg + 4) ^ s)];
            }
            #pragma unroll
            for (int nt = 0; nt < 4; nt++) {
                int n = wn * 32 + nt * 8 + gid;
                int s = (n & 7) << 2;
                bf[nt][0] = bufB[n * BK + ((k0 + tg) ^ s)];
                bf[nt][1] = bufB[n * BK + ((k0 + tg + 4) ^ s)];
            }
            #pragma unroll
            for (int mt = 0; mt < 2; mt++)
                #pragma unroll
                for (int nt = 0; nt < 4; nt++)
                    mma_tf32(c[mt][nt], af[mt], bf[nt]);
        }
        if (has_next) {
            uint32_t* dA = sA + (p ^ 1) * AW;
            uint32_t* dB = sB + (p ^ 1) * BW;
            #pragma unroll
            for (int i = 0; i < 2; i++) {
                int r = lr + i * 32;
                int w = r * BK + (lc ^ ((r & 7) << 2));
                *(uint4*)(dA + w) = make_uint4(f2t(av[i].x), f2t(av[i].y), f2t(av[i].z), f2t(av[i].w));
            }
            #pragma unroll
            for (int i = 0; i < 4; i++) {
                int r = lr + i * 32;
                int w = r * BK + (lc ^ ((r & 7) << 2));
                *(uint4*)(dB + w) = make_uint4(f2t(bv[i].x), f2t(bv[i].y), f2t(bv[i].z), f2t(bv[i].w));
            }
            __syncthreads();
        }
    }

    // ---- epilogue ----
    float* Cz = C + (size_t)blockIdx.z * 512 * ldc;
    #pragma unroll
    for (int mt = 0; mt < 2; mt++) {
        int r0 = m0 + wm * 32 + mt * 16 + gid;
        #pragma unroll
        for (int nt = 0; nt < 4; nt++) {
            int cc = n0 + wn * 32 + nt * 8 + 2 * tg;
            float* p0 = Cz + (size_t)r0 * ldc + cc;
            float* p1 = p0 + 8 * ldc;
            if (cc < N) {
                float bb0 = bias ? bias[cc] : 0.f;
                p0[0] = c[mt][nt][0] + bb0;
                p1[0] = c[mt][nt][2] + bb0;
            }
            if (cc + 1 < N) {
                float bb1 = bias ? bias[cc + 1] : 0.f;
                p0[1] = c[mt][nt][1] + bb1;
                p1[1] = c[mt][nt][3] + bb1;
            }
        }
    }
}

// ---------------- combine: o = act(p0 + p1 + bias) ----------------
template <int ACT>
__global__ void combine(const float* __restrict__ p0, const float* __restrict__ p1,
                        const float* __restrict__ bias, int nmask,
                        float* __restrict__ o, int n)
{
    int i = blockIdx.x * 256 + threadIdx.x;
    if (i < n) {
        float v = p0[i] + p1[i] + bias[i & nmask];
        if (ACT == 1) v = tanhf(v);
        o[i] = v;
    }
}

// ---------------- K1: embedding + concat builders ----------------
__global__ void embed_kernel(const int* __restrict__ input,
                             const int* __restrict__ input_d,
                             const float* __restrict__ hidden,
                             const float* __restrict__ ans,
                             const float* __restrict__ emb_w,
                             const float* __restrict__ emb_d_w,
                             float* __restrict__ ahead,
                             float* __restrict__ minp)
{
    int b = blockIdx.x;
    int t = threadIdx.x;  // 128
    int tok = input[b];
    const float* src;
    if (tok > 2003) {
        int di = tok - 2004;
        if (di > LCC - 1) di = LCC - 1;
        if (di < 0) di = 0;
        int dt = input_d[b * LCC + di];
        src = emb_d_w + (size_t)dt * EE;
    } else {
        int tv = tok < 0 ? 0 : tok;
        src = emb_w + (size_t)tv * EE;
    }
    float* ah = ahead + (size_t)b * GRU_IN;
    float* mp = minp + (size_t)b * MLP_IN;
    for (int j = t; j < EE; j += 128) {
        float e = src[j];
        ah[512 + j] = e;
        mp[1536 + j] = e;
    }
    for (int h = t; h < HH; h += 128) {
        float hv = hidden[(size_t)b * HH + h];
        float av = ans[(size_t)b * HH + h];
        ah[h] = hv;
        ah[812 + h] = av;
        mp[1024 + h] = av;
    }
}

// ---------------- K3: reduce split-K partials + bias, tanh, softmax ----------------
__global__ void attn_finalize(const float* __restrict__ partial,
                              const float* __restrict__ attn_b,
                              float* __restrict__ attnw)
{
    int b = blockIdx.x, t = threadIdx.x;  // 128 threads
    __shared__ float sred[4];
    float v = -1e30f;
    if (t < LCC) {
        float acc = attn_b[t];
        #pragma unroll 6
        for (int s = 0; s < NSPLIT; s++)
            acc += partial[((size_t)s * BB + b) * LCC + t];
        v = tanhf(acc);
    }
    float m = warpReduceMax(v);
    if ((t & 31) == 0) sred[t >> 5] = m;
    __syncthreads();
    m = fmaxf(fmaxf(sred[0], sred[1]), fmaxf(sred[2], sred[3]));
    float e = (t < LCC) ? expf(v - m) : 0.f;
    float ss = warpReduceSum(e);
    __syncthreads();
    if ((t & 31) == 0) sred[t >> 5] = ss;
    __syncthreads();
    float tot = sred[0] + sred[1] + sred[2] + sred[3];
    if (t < LCC) attnw[(size_t)b * LCC + t] = e / tot;
}

// ---------------- K4: c_t = einsum('bl,blh->bh') ----------------
__global__ void ct_kernel(const float* __restrict__ annot,
                          const float* __restrict__ attnw,
                          float* __restrict__ minp)
{
    int b = blockIdx.x, t = threadIdx.x;  // 128
    __shared__ float w[LCC];
    if (t < LCC) w[t] = attnw[(size_t)b * LCC + t];
    __syncthreads();
    const float* Ab = annot + (size_t)b * ANNOT_K;
    for (int h = t; h < HH; h += 128) {
        float acc = 0.f;
        #pragma unroll 4
        for (int l = 0; l < LCC; l++) acc = fmaf(w[l], Ab[l * HH + h], acc);
        minp[(size_t)b * MLP_IN + 512 + h] = acc;
    }
}

// ---------------- K5: GRU elementwise (sums split-K partials inline) ----------------
__global__ void gru_kernel(const float* __restrict__ giP,
                           const float* __restrict__ ghP,
                           const float* __restrict__ b_ih,
                           const float* __restrict__ b_hh,
                           const float* __restrict__ h0,
                           float* __restrict__ minp,
                           float* __restrict__ out0,
                           float* __restrict__ out1)
{
    int i = blockIdx.x * blockDim.x + threadIdx.x;  // 512*512
    int b = i >> 9, h = i & 511;
    size_t o = (size_t)b * 1536;
    const float* g0 = giP + o;
    const float* g1 = giP + 786432 + o;   // 512*1536
    const float* q0 = ghP + o;
    const float* q1 = ghP + 786432 + o;
    float ir = g0[h] + g1[h] + b_ih[h];
    float iz = g0[512 + h] + g1[512 + h] + b_ih[512 + h];
    float in_ = g0[1024 + h] + g1[1024 + h] + b_ih[1024 + h];
    float hr = q0[h] + q1[h] + b_hh[h];
    float hz = q0[512 + h] + q1[512 + h] + b_hh[512 + h];
    float hn = q0[1024 + h] + q1[1024 + h] + b_hh[1024 + h];
    float r = 1.f / (1.f + expf(-(ir + hr)));
    float z = 1.f / (1.f + expf(-(iz + hz)));
    float n = tanhf(in_ + r * hn);
    float hnew = (1.f - z) * n + z * h0[i];
    minp[(size_t)b * MLP_IN + h] = hnew;
    out0[i] = hnew;
    out1[i] = hnew;
}

// ---------------- K6: z_t + output softmax + log, write p_t ----------------
__global__ void final_kernel(const float* __restrict__ olog,
                             const float* __restrict__ z2,
                             const float* __restrict__ zt_W3,
                             const float* __restrict__ zt_b3,
                             const float* __restrict__ attnw,
                             float* __restrict__ pout)
{
    int b = blockIdx.x, t = threadIdx.x;  // 256 threads, 8 warps
    __shared__ float sred[8];
    __shared__ float sbc;

    float s = 0.f;
    for (int h = t; h < HH; h += 256) s = fmaf(z2[(size_t)b * HH + h], zt_W3[h], s);
    s = warpReduceSum(s);
    if ((t & 31) == 0) sred[t >> 5] = s;
    __syncthreads();
    if (t == 0) {
        float tot = 0.f;
        for (int w = 0; w < 8; w++) tot += sred[w];
        sbc = 1.f / (1.f + expf(-(tot + zt_b3[0])));
    }
    __syncthreads();
    float zt = sbc;

    const float* ob = olog + (size_t)b * OO;
    float mx = -1e30f;
    for (int j = t; j < OO; j += 256) mx = fmaxf(mx, ob[j]);
    mx = warpReduceMax(mx);
    __syncthreads();
    if ((t & 31) == 0) sred[t >> 5] = mx;
    __syncthreads();
    if (t == 0) {
        float mm = sred[0];
        for (int w = 1; w < 8; w++) mm = fmaxf(mm, sred[w]);
        sbc = mm;
    }
    __syncthreads();
    mx = sbc;

    float se = 0.f;
    for (int j = t; j < OO; j += 256) se += expf(ob[j] - mx);
    se = warpReduceSum(se);
    __syncthreads();
    if ((t & 31) == 0) sred[t >> 5] = se;
    __syncthreads();
    if (t == 0) {
        float tot = 0.f;
        for (int w = 0; w < 8; w++) tot += sred[w];
        sbc = tot;
    }
    __syncthreads();
    float inv = 1.f / sbc;

    float* pb = pout + (size_t)b * (OO + LCC);
    for (int j = t; j < OO; j += 256)
        pb[j] = logf(expf(ob[j] - mx) * inv * zt + 1e-20f);
    float omz = 1.f - zt;
    for (int l = t; l < LCC; l += 256)
        pb[OO + l] = logf(attnw[(size_t)b * LCC + l] * omz + 1e-20f);
}

// ---------------- launch ----------------
extern "C" void kernel_launch(void* const* d_in, const int* in_sizes, int n_in,
                              void* d_out, int out_size)
{
    const int*   input   = (const int*)d_in[0];
    const int*   input_d = (const int*)d_in[1];
    const float* hidden  = (const float*)d_in[2];
    const float* annot   = (const float*)d_in[3];
    const float* ans     = (const float*)d_in[4];
    const float* emb_w   = (const float*)d_in[5];
    const float* emb_d_w = (const float*)d_in[6];
    const float* attn_W  = (const float*)d_in[7];
    const float* attn_b  = (const float*)d_in[8];
    const float* W_ih    = (const float*)d_in[9];
    const float* W_hh    = (const float*)d_in[10];
    const float* b_ih    = (const float*)d_in[11];
    const float* b_hh    = (const float*)d_in[12];
    const float* mlp_W   = (const float*)d_in[13];
    const float* mlp_b   = (const float*)d_in[14];
    const float* out_W   = (const float*)d_in[15];
    const float* out_b   = (const float*)d_in[16];
    const float* zt_W1   = (const float*)d_in[17];
    const float* zt_b1   = (const float*)d_in[18];
    const float* zt_W2   = (const float*)d_in[19];
    const float* zt_b2   = (const float*)d_in[20];
    const float* zt_W3   = (const float*)d_in[21];
    const float* zt_b3   = (const float*)d_in[22];
    float* out = (float*)d_out;

    float* scr = nullptr;
    cudaGetSymbolAddress((void**)&scr, g_scratch);
    float* ahead = scr + OFF_AHEAD;
    float* minp  = scr + OFF_MINP;
    float* part  = scr + OFF_PART;
    float* attnw = scr + OFF_ATTNW;
    float* giP   = scr + OFF_GIP;
    float* ghP   = scr + OFF_GHP;
    float* etP   = scr + OFF_ETP;
    float* et    = scr + OFF_ET;
    float* ologs = scr + OFF_OLOG;
    float* z1P   = scr + OFF_Z1P;
    float* z1    = scr + OFF_Z1;
    float* z2P   = scr + OFF_Z2P;
    float* z2    = scr + OFF_Z2;

    cudaFuncSetAttribute(tmma, cudaFuncAttributeMaxDynamicSharedMemorySize, TMMA_SMEM);

    // 1. embedding + concat staging
    embed_kernel<<<BB, 128>>>(input, input_d, hidden, ans, emb_w, emb_d_w, ahead, minp);
    // 2. attention logits: annot part (64 K-splits) + head part (8 K-splits)
    tmma<<<dim3(8, 1, 64), 256, TMMA_SMEM>>>(
        LCC, ANNOT_K, 800, annot, ANNOT_K, attn_W + GRU_IN, ATTN_IN, nullptr, part, LCC);
    tmma<<<dim3(8, 1, 8), 256, TMMA_SMEM>>>(
        LCC, GRU_IN, 168, ahead, GRU_IN, attn_W, ATTN_IN, nullptr,
        part + (size_t)64 * BB * LCC, LCC);
    attn_finalize<<<BB, 128>>>(part, attn_b, attnw);
    // 3. context vector
    ct_kernel<<<BB, 128>>>(annot, attnw, minp);
    // 4. GRU (both gate GEMMs split-K x2; gru_kernel sums partials + bias)
    tmma<<<dim3(8, 12, 2), 256, TMMA_SMEM>>>(
        1536, GRU_IN, 664, minp + 512, MLP_IN, W_ih, GRU_IN, nullptr, giP, 1536);
    tmma<<<dim3(8, 12, 2), 256, TMMA_SMEM>>>(
        1536, HH, 256, hidden, HH, W_hh, HH, nullptr, ghP, 1536);
    gru_kernel<<<1024, 256>>>(giP, ghP, b_ih, b_hh, hidden, minp, out, out + BB * HH);
    // 5. mlp (split-K x2 + combine) + output head
    tmma<<<dim3(8, 4, 2), 256, TMMA_SMEM>>>(
        HH, MLP_IN, 920, minp, MLP_IN, mlp_W, MLP_IN, nullptr, etP, HH);
    combine<0><<<1024, 256>>>(etP, etP + 512 * 512, mlp_b, 511, et, 512 * 512);
    tmma<<<dim3(8, 16, 1), 256, TMMA_SMEM>>>(
        OO, HH, HH, et, HH, out_W, HH, out_b, ologs, OO);
    // 6. z gate (split-K x2 + tanh combines)
    tmma<<<dim3(8, 8, 2), 256, TMMA_SMEM>>>(
        1024, MLP_IN, 920, minp, MLP_IN, zt_W1, MLP_IN, nullptr, z1P, 1024);
    combine<1><<<2048, 256>>>(z1P, z1P + 512 * 1024, zt_b1, 1023, z1, 512 * 1024);
    tmma<<<dim3(8, 4, 2), 256, TMMA_SMEM>>>(
        HH, 1024, 512, z1, 1024, zt_W2, 1024, nullptr, z2P, HH);
    combine<1><<<1024, 256>>>(z2P, z2P + 512 * 512, zt_b2, 511, z2, 512 * 512);
    // 7. final softmax/log + p_t
    final_kernel<<<BB, 256>>>(ologs, z2, zt_W3, zt_b3, attnw, out + 2 * BB * HH);
}

// round 4
// speedup vs baseline: 4.1906x; 1.4529x over previous
#include <cuda_runtime.h>
#include <cstdint>
#include <math.h>

// ---------------- problem constants ----------------
#define BB 512
#define HH 512
#define EE 300
#define LCC 100
#define OO 2004
#define ATTN_IN 52524      // H*(LC+2)+E
#define GRU_IN 1324        // 2H+E
#define MLP_IN 1836        // 3H+E
#define ANNOT_K 51200      // LC*H
#define NSPLIT 68          // 64 annot splits + 4 head splits

// ---------------- scratch (device globals) ----------------
#define OFF_AHEAD 0                      // 512*1324
#define OFF_MINP  677888UL               // 512*1836
#define OFF_PART  1617920UL              // 512*6800  ([b][s][l])
#define OFF_ATTNW 5099520UL              // 512*100
#define OFF_GIP   5150720UL              // 2*512*1536
#define OFF_GHP   6723584UL              // 2*512*1536
#define OFF_ETP   8296448UL              // 8*512*512
#define OFF_ET    10393600UL             // 512*512
#define OFF_OLOG  10655744UL             // 512*2004
#define OFF_Z1P   11681792UL             // 4*512*1024
#define OFF_Z1    13778944UL             // 512*1024
#define OFF_Z2P   14303232UL             // 4*512*512
#define OFF_Z2    15351808UL             // 512*512
#define SCRATCH_TOTAL 15613952UL

__device__ float g_scratch[SCRATCH_TOTAL];

// ---------------- low-level helpers ----------------
__device__ __forceinline__ uint32_t smem_u32(const void* p) {
    uint32_t a;
    asm("{ .reg .u64 t; cvta.to.shared.u64 t, %1; cvt.u32.u64 %0, t; }"
        : "=r"(a) : "l"(p));
    return a;
}
__device__ __forceinline__ void cpasync16(uint32_t dst, const void* src, int sz) {
    asm volatile("cp.async.cg.shared.global [%0], [%1], 16, %2;"
                 :: "r"(dst), "l"(src), "r"(sz) : "memory");
}
#define CP_COMMIT() asm volatile("cp.async.commit_group;" ::: "memory")
#define CP_WAIT0()  asm volatile("cp.async.wait_group 0;" ::: "memory")
#define LDSM4(r0, r1, r2, r3, addr) \
    asm volatile("ldmatrix.sync.aligned.m8n8.x4.shared.b16 {%0,%1,%2,%3}, [%4];" \
        : "=r"(r0), "=r"(r1), "=r"(r2), "=r"(r3) : "r"(addr))
__device__ __forceinline__ void mma_tf32(float* c, const uint32_t* a, const uint32_t* b) {
    asm volatile(
        "mma.sync.aligned.m16n8k8.row.col.f32.tf32.tf32.f32 "
        "{%0,%1,%2,%3}, {%4,%5,%6,%7}, {%8,%9}, {%0,%1,%2,%3};"
        : "+f"(c[0]), "+f"(c[1]), "+f"(c[2]), "+f"(c[3])
        : "r"(a[0]), "r"(a[1]), "r"(a[2]), "r"(a[3]), "r"(b[0]), "r"(b[1]));
}
__device__ __forceinline__ float warpReduceSum(float v) {
    #pragma unroll
    for (int o = 16; o > 0; o >>= 1) v += __shfl_xor_sync(0xffffffffu, v, o);
    return v;
}
__device__ __forceinline__ float warpReduceMax(float v) {
    #pragma unroll
    for (int o = 16; o > 0; o >>= 1) v = fmaxf(v, __shfl_xor_sync(0xffffffffu, v, o));
    return v;
}

// ================= tf32 mma GEMM v2: C = A(M,K) @ B(N,K)^T =================
// BM=128, BN=128, BK=32. 8 warps (2m x 4n), warp tile 64x32.
// cp.async 2-stage pipeline, ldmatrix.x4 fragment loads, XOR-16B swizzle.
// Split-K: slice z written at C + z*zstride, K range [z*KC, min(z*KC+KC,K)).
#define TMMA_SMEM 65536

__device__ __forceinline__ void tmma_issue(
    uint32_t smbase, int p, int kk, int kend,
    const float* A, int lda, const float* B, int ldb,
    int m0, int n0, int N, int lr, int c16)
{
    const int kc = kk + (c16 << 2);
    const bool kok = (kc + 4 <= kend);
    const int szk = kok ? 16 : 0;
    #pragma unroll
    for (int i = 0; i < 4; i++) {
        int row = lr + (i << 5);
        const float* src = kok ? (A + (size_t)(m0 + row) * lda + kc) : A;
        uint32_t dst = smbase + p * 32768 + row * 128 + ((c16 ^ (row & 7)) << 4);
        cpasync16(dst, src, szk);
    }
    #pragma unroll
    for (int i = 0; i < 4; i++) {
        int row = lr + (i << 5);
        int n = n0 + row;
        bool ok = kok && (n < N);
        int sz = ok ? 16 : 0;
        const float* src = ok ? (B + (size_t)n * ldb + kc) : B;
        uint32_t dst = smbase + p * 32768 + 16384 + row * 128 + ((c16 ^ (row & 7)) << 4);
        cpasync16(dst, src, sz);
    }
    CP_COMMIT();
}

template <int ACT>
__global__ void __launch_bounds__(256, 2) tmma(
    int N, int K, int KC, long zstride,
    const float* __restrict__ A, int lda,
    const float* __restrict__ B, int ldb,
    const float* __restrict__ bias,
    float* __restrict__ C, int ldc)
{
    extern __shared__ __align__(1024) uint32_t sm[];
    const int tid = threadIdx.x;
    const int lane = tid & 31, wid = tid >> 5;
    const int wm = wid & 1, wn = wid >> 1;
    const int gid = lane >> 2, tg = lane & 3;

    const int m0 = blockIdx.x << 7;
    const int n0 = blockIdx.y << 7;
    const int kstart = blockIdx.z * KC;
    int kend = kstart + KC; if (kend > K) kend = K;
    const int nb = (kend - kstart + 31) >> 5;

    const uint32_t smbase = smem_u32(sm);
    const int lr = tid >> 3, c16 = tid & 7;

    // fragment-load address precompute
    const int ahi = (lane >> 4) & 1;            // A chunk select
    const int bhi = (lane >> 3) & 1;            // B chunk select
    uint32_t aoff[4]; int asw[4];
    #pragma unroll
    for (int mt = 0; mt < 4; mt++) {
        int r = wm * 64 + mt * 16 + (lane & 7) + (lane & 8);
        aoff[mt] = r * 128;
        asw[mt] = r & 7;
    }
    uint32_t boff[2]; int bsw[2];
    #pragma unroll
    for (int nn = 0; nn < 2; nn++) {
        int r = wn * 32 + nn * 16 + (lane & 7) + ((lane & 16) >> 1);
        boff[nn] = 16384 + r * 128;
        bsw[nn] = r & 7;
    }

    float c[4][4][4];
    #pragma unroll
    for (int i = 0; i < 4; i++)
        #pragma unroll
        for (int j = 0; j < 4; j++)
            #pragma unroll
            for (int q = 0; q < 4; q++) c[i][j][q] = 0.f;

    // prologue
    tmma_issue(smbase, 0, kstart, kend, A, lda, B, ldb, m0, n0, N, lr, c16);
    CP_WAIT0();
    __syncthreads();

    for (int kb = 0; kb < nb; kb++) {
        const int p = kb & 1;
        const bool nxt = (kb + 1 < nb);
        if (nxt)
            tmma_issue(smbase, p ^ 1, kstart + (kb + 1) * 32, kend,
                       A, lda, B, ldb, m0, n0, N, lr, c16);
        const uint32_t sp = smbase + p * 32768;
        #pragma unroll
        for (int ks = 0; ks < 4; ks++) {
            uint32_t af[4][4], bf[4][2];
            #pragma unroll
            for (int mt = 0; mt < 4; mt++) {
                uint32_t ad = sp + aoff[mt] + ((((ks << 1) + ahi) ^ asw[mt]) << 4);
                LDSM4(af[mt][0], af[mt][1], af[mt][2], af[mt][3], ad);
            }
            #pragma unroll
            for (int nn = 0; nn < 2; nn++) {
                uint32_t r0, r1, r2, r3;
                uint32_t bd = sp + boff[nn] + ((((ks << 1) + bhi) ^ bsw[nn]) << 4);
                LDSM4(r0, r1, r2, r3, bd);
                bf[nn * 2][0] = r0; bf[nn * 2][1] = r1;
                bf[nn * 2 + 1][0] = r2; bf[nn * 2 + 1][1] = r3;
            }
            #pragma unroll
            for (int mt = 0; mt < 4; mt++)
                #pragma unroll
                for (int nt = 0; nt < 4; nt++)
                    mma_tf32(c[mt][nt], af[mt], bf[nt]);
        }
        if (nxt) { CP_WAIT0(); __syncthreads(); }
    }

    // epilogue
    float* Cz = C + (size_t)blockIdx.z * zstride;
    #pragma unroll
    for (int mt = 0; mt < 4; mt++) {
        int r0 = m0 + wm * 64 + mt * 16 + gid;
        #pragma unroll
        for (int nt = 0; nt < 4; nt++) {
            int cc = n0 + wn * 32 + nt * 8 + 2 * tg;
            float* p0 = Cz + (size_t)r0 * ldc + cc;
            float* p1 = p0 + 8 * ldc;
            if (cc < N) {
                float bb = bias ? bias[cc] : 0.f;
                float v0 = c[mt][nt][0] + bb;
                float v1 = c[mt][nt][2] + bb;
                if (ACT == 1) { v0 = tanhf(v0); v1 = tanhf(v1); }
                p0[0] = v0; p1[0] = v1;
            }
            if (cc + 1 < N) {
                float bb = bias ? bias[cc + 1] : 0.f;
                float v0 = c[mt][nt][1] + bb;
                float v1 = c[mt][nt][3] + bb;
                if (ACT == 1) { v0 = tanhf(v0); v1 = tanhf(v1); }
                p0[1] = v0; p1[1] = v1;
            }
        }
    }
}

// ---------------- combine: o = act(sum_j p[i + j*pstride] + bias) ----------------
template <int ACT>
__global__ void combine(const float* __restrict__ p, int nparts, int pstride,
                        const float* __restrict__ bias, int nmask,
                        float* __restrict__ o, int n)
{
    int i = blockIdx.x * 256 + threadIdx.x;
    if (i >= n) return;
    float v = bias[i & nmask];
    for (int j = 0; j < nparts; j++) v += p[i + (size_t)j * pstride];
    if (ACT == 1) v = tanhf(v);
    o[i] = v;
}

// ---------------- K1: embedding + concat builders ----------------
__global__ void embed_kernel(const int* __restrict__ input,
                             const int* __restrict__ input_d,
                             const float* __restrict__ hidden,
                             const float* __restrict__ ans,
                             const float* __restrict__ emb_w,
                             const float* __restrict__ emb_d_w,
                             float* __restrict__ ahead,
                             float* __restrict__ minp)
{
    int b = blockIdx.x;
    int t = threadIdx.x;  // 128
    int tok = input[b];
    const float* src;
    if (tok > 2003) {
        int di = tok - 2004;
        if (di > LCC - 1) di = LCC - 1;
        if (di < 0) di = 0;
        int dt = input_d[b * LCC + di];
        src = emb_d_w + (size_t)dt * EE;
    } else {
        int tv = tok < 0 ? 0 : tok;
        src = emb_w + (size_t)tv * EE;
    }
    float* ah = ahead + (size_t)b * GRU_IN;
    float* mp = minp + (size_t)b * MLP_IN;
    for (int j = t; j < EE; j += 128) {
        float e = src[j];
        ah[512 + j] = e;
        mp[1536 + j] = e;
    }
    for (int h = t; h < HH; h += 128) {
        float hv = hidden[(size_t)b * HH + h];
        float av = ans[(size_t)b * HH + h];
        ah[h] = hv;
        ah[812 + h] = av;
        mp[1024 + h] = av;
    }
}

// ---------------- K3: reduce split-K partials + bias, tanh, softmax ----------------
// partial layout: [b][s][l], contiguous 6800 floats per batch row.
__global__ void attn_finalize(const float* __restrict__ partial,
                              const float* __restrict__ attn_b,
                              float* __restrict__ attnw)
{
    int b = blockIdx.x, t = threadIdx.x;  // 128 threads
    __shared__ float sred[4];
    const float* pb = partial + (size_t)b * (NSPLIT * LCC);
    float v = -1e30f;
    if (t < LCC) {
        float acc = attn_b[t];
        #pragma unroll 4
        for (int s = 0; s < NSPLIT; s++)
            acc += pb[s * LCC + t];
        v = tanhf(acc);
    }
    float m = warpReduceMax(v);
    if ((t & 31) == 0) sred[t >> 5] = m;
    __syncthreads();
    m = fmaxf(fmaxf(sred[0], sred[1]), fmaxf(sred[2], sred[3]));
    float e = (t < LCC) ? __expf(v - m) : 0.f;
    float ss = warpReduceSum(e);
    __syncthreads();
    if ((t & 31) == 0) sred[t >> 5] = ss;
    __syncthreads();
    float tot = sred[0] + sred[1] + sred[2] + sred[3];
    if (t < LCC) attnw[(size_t)b * LCC + t] = e / tot;
}

// ---------------- K4: c_t = einsum('bl,blh->bh') (float4) ----------------
__global__ void ct_kernel(const float* __restrict__ annot,
                          const float* __restrict__ attnw,
                          float* __restrict__ minp)
{
    int b = blockIdx.x, t = threadIdx.x;  // 128 -> 4 h each
    __shared__ float w[LCC];
    if (t < LCC) w[t] = attnw[(size_t)b * LCC + t];
    __syncthreads();
    const float4* Ab = (const float4*)(annot + (size_t)b * ANNOT_K);
    float ax = 0.f, ay = 0.f, az = 0.f, aw = 0.f;
    #pragma unroll 4
    for (int l = 0; l < LCC; l++) {
        float4 v = Ab[l * 128 + t];
        float wl = w[l];
        ax = fmaf(wl, v.x, ax); ay = fmaf(wl, v.y, ay);
        az = fmaf(wl, v.z, az); aw = fmaf(wl, v.w, aw);
    }
    *(float4*)(minp + (size_t)b * MLP_IN + 512 + 4 * t) = make_float4(ax, ay, az, aw);
}

// ---------------- K5: GRU elementwise (sums 2 split-K partials inline) ----------------
__global__ void gru_kernel(const float* __restrict__ giP,
                           const float* __restrict__ ghP,
                           const float* __restrict__ b_ih,
                           const float* __restrict__ b_hh,
                           const float* __restrict__ h0,
                           float* __restrict__ minp,
                           float* __restrict__ out0,
                           float* __restrict__ out1)
{
    int i = blockIdx.x * blockDim.x + threadIdx.x;  // 512*512
    int b = i >> 9, h = i & 511;
    size_t o = (size_t)b * 1536;
    const float* g0 = giP + o;
    const float* g1 = giP + 786432 + o;
    const float* q0 = ghP + o;
    const float* q1 = ghP + 786432 + o;
    float ir = g0[h] + g1[h] + b_ih[h];
    float iz = g0[512 + h] + g1[512 + h] + b_ih[512 + h];
    float in_ = g0[1024 + h] + g1[1024 + h] + b_ih[1024 + h];
    float hr = q0[h] + q1[h] + b_hh[h];
    float hz = q0[512 + h] + q1[512 + h] + b_hh[512 + h];
    float hn = q0[1024 + h] + q1[1024 + h] + b_hh[1024 + h];
    float r = 1.f / (1.f + __expf(-(ir + hr)));
    float z = 1.f / (1.f + __expf(-(iz + hz)));
    float n = tanhf(in_ + r * hn);
    float hnew = (1.f - z) * n + z * h0[i];
    minp[(size_t)b * MLP_IN + h] = hnew;
    out0[i] = hnew;
    out1[i] = hnew;
}

// ---------------- K6: z_t + output softmax + log, write p_t ----------------
__global__ void final_kernel(const float* __restrict__ olog,
                             const float* __restrict__ z2,
                             const float* __restrict__ zt_W3,
                             const float* __restrict__ zt_b3,
                             const float* __restrict__ attnw,
                             float* __restrict__ pout)
{
    __shared__ float buf[OO];
    __shared__ float sred[8];
    __shared__ float sbc;
    int b = blockIdx.x, t = threadIdx.x;  // 256 threads

    // z_t
    float s = 0.f;
    for (int h = t; h < HH; h += 256) s = fmaf(z2[(size_t)b * HH + h], zt_W3[h], s);
    s = warpReduceSum(s);
    if ((t & 31) == 0) sred[t >> 5] = s;
    __syncthreads();
    if (t == 0) {
        float tot = 0.f;
        for (int w = 0; w < 8; w++) tot += sred[w];
        sbc = 1.f / (1.f + __expf(-(tot + zt_b3[0])));
    }
    __syncthreads();
    float zt = sbc;

    // load logits into smem + max
    const float* ob = olog + (size_t)b * OO;
    float mx = -1e30f;
    for (int j = t; j < OO; j += 256) {
        float v = ob[j];
        buf[j] = v;
        mx = fmaxf(mx, v);
    }
    mx = warpReduceMax(mx);
    __syncthreads();
    if ((t & 31) == 0) sred[t >> 5] = mx;
    __syncthreads();
    if (t == 0) {
        float mm = sred[0];
        for (int w = 1; w < 8; w++) mm = fmaxf(mm, sred[w]);
        sbc = mm;
    }
    __syncthreads();
    mx = sbc;

    // exp + sum (exp cached in smem)
    float se = 0.f;
    for (int j = t; j < OO; j += 256) {
        float e = __expf(buf[j] - mx);
        buf[j] = e;
        se += e;
    }
    se = warpReduceSum(se);
    __syncthreads();
    if ((t & 31) == 0) sred[t >> 5] = se;
    __syncthreads();
    if (t == 0) {
        float tot = 0.f;
        for (int w = 0; w < 8; w++) tot += sred[w];
        sbc = tot;
    }
    __syncthreads();
    float cc = zt / sbc;

    float* pb = pout + (size_t)b * (OO + LCC);
    for (int j = t; j < OO; j += 256)
        pb[j] = __logf(buf[j] * cc + 1e-20f);
    float omz = 1.f - zt;
    for (int l = t; l < LCC; l += 256)
        pb[OO + l] = __logf(attnw[(size_t)b * LCC + l] * omz + 1e-20f);
}

// ---------------- launch ----------------
extern "C" void kernel_launch(void* const* d_in, const int* in_sizes, int n_in,
                              void* d_out, int out_size)
{
    const int*   input   = (const int*)d_in[0];
    const int*   input_d = (const int*)d_in[1];
    const float* hidden  = (const float*)d_in[2];
    const float* annot   = (const float*)d_in[3];
    const float* ans     = (const float*)d_in[4];
    const float* emb_w   = (const float*)d_in[5];
    const float* emb_d_w = (const float*)d_in[6];
    const float* attn_W  = (const float*)d_in[7];
    const float* attn_b  = (const float*)d_in[8];
    const float* W_ih    = (const float*)d_in[9];
    const float* W_hh    = (const float*)d_in[10];
    const float* b_ih    = (const float*)d_in[11];
    const float* b_hh    = (const float*)d_in[12];
    const float* mlp_W   = (const float*)d_in[13];
    const float* mlp_b   = (const float*)d_in[14];
    const float* out_W   = (const float*)d_in[15];
    const float* out_b   = (const float*)d_in[16];
    const float* zt_W1   = (const float*)d_in[17];
    const float* zt_b1   = (const float*)d_in[18];
    const float* zt_W2   = (const float*)d_in[19];
    const float* zt_b2   = (const float*)d_in[20];
    const float* zt_W3   = (const float*)d_in[21];
    const float* zt_b3   = (const float*)d_in[22];
    float* out = (float*)d_out;

    float* scr = nullptr;
    cudaGetSymbolAddress((void**)&scr, g_scratch);
    float* ahead = scr + OFF_AHEAD;
    float* minp  = scr + OFF_MINP;
    float* part  = scr + OFF_PART;
    float* attnw = scr + OFF_ATTNW;
    float* giP   = scr + OFF_GIP;
    float* ghP   = scr + OFF_GHP;
    float* etP   = scr + OFF_ETP;
    float* et    = scr + OFF_ET;
    float* ologs = scr + OFF_OLOG;
    float* z1P   = scr + OFF_Z1P;
    float* z1    = scr + OFF_Z1;
    float* z2P   = scr + OFF_Z2P;
    float* z2    = scr + OFF_Z2;

    cudaFuncSetAttribute(tmma<0>, cudaFuncAttributeMaxDynamicSharedMemorySize, TMMA_SMEM);

    // 1. embedding + concat staging
    embed_kernel<<<BB, 128>>>(input, input_d, hidden, ans, emb_w, emb_d_w, ahead, minp);
    // 2. attention logits: annot (64 K-splits) + head (4 K-splits); partials [b][s][l]
    tmma<0><<<dim3(4, 1, 64), 256, TMMA_SMEM>>>(
        LCC, ANNOT_K, 800, LCC, annot, ANNOT_K, attn_W + GRU_IN, ATTN_IN,
        nullptr, part, NSPLIT * LCC);
    tmma<0><<<dim3(4, 1, 4), 256, TMMA_SMEM>>>(
        LCC, GRU_IN, 332, LCC, ahead, GRU_IN, attn_W, ATTN_IN,
        nullptr, part + 64 * LCC, NSPLIT * LCC);
    attn_finalize<<<BB, 128>>>(part, attn_b, attnw);
    // 3. context vector
    ct_kernel<<<BB, 128>>>(annot, attnw, minp);
    // 4. GRU (both gate GEMMs split-K x2; gru_kernel sums partials + bias)
    tmma<0><<<dim3(4, 12, 2), 256, TMMA_SMEM>>>(
        1536, GRU_IN, 664, 786432, minp + 512, MLP_IN, W_ih, GRU_IN, nullptr, giP, 1536);
    tmma<0><<<dim3(4, 12, 2), 256, TMMA_SMEM>>>(
        1536, HH, 256, 786432, hidden, HH, W_hh, HH, nullptr, ghP, 1536);
    gru_kernel<<<1024, 256>>>(giP, ghP, b_ih, b_hh, hidden, minp, out, out + BB * HH);
    // 5. mlp (split-K x8 + combine) + output head
    tmma<0><<<dim3(4, 4, 8), 256, TMMA_SMEM>>>(
        HH, MLP_IN, 256, 262144, minp, MLP_IN, mlp_W, MLP_IN, nullptr, etP, HH);
    combine<0><<<1024, 256>>>(etP, 8, 262144, mlp_b, 511, et, 262144);
    tmma<0><<<dim3(4, 16, 1), 256, TMMA_SMEM>>>(
        OO, HH, HH, 0, et, HH, out_W, HH, out_b, ologs, OO);
    // 6. z gate (split-K + tanh combines)
    tmma<0><<<dim3(4, 8, 4), 256, TMMA_SMEM>>>(
        1024, MLP_IN, 480, 524288, minp, MLP_IN, zt_W1, MLP_IN, nullptr, z1P, 1024);
    combine<1><<<2048, 256>>>(z1P, 4, 524288, zt_b1, 1023, z1, 524288);
    tmma<0><<<dim3(4, 4, 4), 256, TMMA_SMEM>>>(
        HH, 1024, 256, 262144, z1, 1024, zt_W2, 1024, nullptr, z2P, HH);
    combine<1><<<1024, 256>>>(z2P, 4, 262144, zt_b2, 511, z2, 262144);
    // 7. final softmax/log + p_t
    final_kernel<<<BB, 256>>>(ologs, z2, zt_W3, zt_b3, attnw, out + 2 * BB * HH);
}

// round 5
// speedup vs baseline: 5.3826x; 1.2844x over previous
#include <cuda_runtime.h>
#include <cstdint>
#include <math.h>

// ---------------- problem constants ----------------
#define BB 512
#define HH 512
#define EE 300
#define LCC 100
#define OO 2004
#define ATTN_IN 52524      // H*(LC+2)+E
#define GRU_IN 1324        // 2H+E
#define MLP_IN 1836        // 3H+E
#define ANNOT_K 51200      // LC*H
#define NSPLIT 68          // 64 annot + 4 head splits

// ---------------- scratch (device globals) ----------------
#define OFF_AHEAD 0UL                    // 512*1324
#define OFF_MINP  677888UL               // 512*1836
#define OFF_PART  1617920UL              // 512*6800  ([b][s][l])
#define OFF_ATTNW 5099520UL              // 512*100
#define OFF_GIP   5150720UL              // 2*512*1536
#define OFF_GHP   6723584UL              // 2*512*1536
#define OFF_ETP   8296448UL              // 8*512*512
#define OFF_ET    10393600UL             // 512*512
#define OFF_OLOG  10655744UL             // 512*2004
#define OFF_Z1P   11681792UL             // 4*512*1024
#define OFF_Z1    13778944UL             // 512*1024
#define OFF_Z2P   14303232UL             // 4*512*512
#define SCRATCH_TOTAL 15351808UL

__device__ float g_scratch[SCRATCH_TOTAL];

// ---------------- low-level helpers ----------------
__device__ __forceinline__ uint32_t smem_u32(const void* p) {
    uint32_t a;
    asm("{ .reg .u64 t; cvta.to.shared.u64 t, %1; cvt.u32.u64 %0, t; }"
        : "=r"(a) : "l"(p));
    return a;
}
__device__ __forceinline__ void cpasync16(uint32_t dst, const void* src, int sz) {
    asm volatile("cp.async.cg.shared.global [%0], [%1], 16, %2;"
                 :: "r"(dst), "l"(src), "r"(sz) : "memory");
}
#define CP_COMMIT() asm volatile("cp.async.commit_group;" ::: "memory")
#define CP_WAIT1()  asm volatile("cp.async.wait_group 1;" ::: "memory")
#define LDSM4(r0, r1, r2, r3, addr) \
    asm volatile("ldmatrix.sync.aligned.m8n8.x4.shared.b16 {%0,%1,%2,%3}, [%4];" \
        : "=r"(r0), "=r"(r1), "=r"(r2), "=r"(r3) : "r"(addr))
__device__ __forceinline__ void mma_tf32(float* c, const uint32_t* a, const uint32_t* b) {
    asm volatile(
        "mma.sync.aligned.m16n8k8.row.col.f32.tf32.tf32.f32 "
        "{%0,%1,%2,%3}, {%4,%5,%6,%7}, {%8,%9}, {%0,%1,%2,%3};"
        : "+f"(c[0]), "+f"(c[1]), "+f"(c[2]), "+f"(c[3])
        : "r"(a[0]), "r"(a[1]), "r"(a[2]), "r"(a[3]), "r"(b[0]), "r"(b[1]));
}
__device__ __forceinline__ float warpReduceSum(float v) {
    #pragma unroll
    for (int o = 16; o > 0; o >>= 1) v += __shfl_xor_sync(0xffffffffu, v, o);
    return v;
}
__device__ __forceinline__ float warpReduceMax(float v) {
    #pragma unroll
    for (int o = 16; o > 0; o >>= 1) v = fmaxf(v, __shfl_xor_sync(0xffffffffu, v, o));
    return v;
}

// ================= descriptor-fused tf32 mma GEMM: C = A(M,K) @ B(N,K)^T ============
// BM=128, BN=128, BK=32, 8 warps (2m x 4n), warp tile 64x32, 3-stage cp.async.
// Two GEMMs per launch; CTA picks its descriptor by linear blockIdx.x.
struct GDesc {
    const float* A; const float* B; const float* bias; float* C;
    int lda, ldb, ldc, N, K, KC;
    long zstride;
    int ntiles, ctasPerZ, nCtas;
};
#define TMMA_SMEM 98304   // 3 stages x (16KB A + 16KB B)

__device__ __forceinline__ void tmma_issue(
    uint32_t smbase, int p, int kk, int kend,
    const float* A, int lda, const float* B, int ldb,
    int m0, int n0, int N, int lr, int c16)
{
    const int kc = kk + (c16 << 2);
    const bool kok = (kc + 4 <= kend);
    const int szk = kok ? 16 : 0;
    #pragma unroll
    for (int i = 0; i < 4; i++) {
        int row = lr + (i << 5);
        const float* src = kok ? (A + (size_t)(m0 + row) * lda + kc) : A;
        uint32_t dst = smbase + p * 32768 + row * 128 + ((c16 ^ (row & 7)) << 4);
        cpasync16(dst, src, szk);
    }
    #pragma unroll
    for (int i = 0; i < 4; i++) {
        int row = lr + (i << 5);
        int n = n0 + row;
        bool ok = kok && (n < N);
        int sz = ok ? 16 : 0;
        const float* src = ok ? (B + (size_t)n * ldb + kc) : B;
        uint32_t dst = smbase + p * 32768 + 16384 + row * 128 + ((c16 ^ (row & 7)) << 4);
        cpasync16(dst, src, sz);
    }
    CP_COMMIT();
}

__global__ void __launch_bounds__(256, 2) tmma2(GDesc d0, GDesc d1)
{
    extern __shared__ __align__(1024) uint32_t sm[];
    const int tid = threadIdx.x;
    const int lane = tid & 31, wid = tid >> 5;
    const int wm = wid & 1, wn = wid >> 1;
    const int gid = lane >> 2, tg = lane & 3;

    // ---- descriptor decode ----
    int bx = blockIdx.x;
    const GDesc& d = (bx < d0.nCtas) ? d0 : d1;
    if (bx >= d0.nCtas) bx -= d0.nCtas;
    const int z = bx / d.ctasPerZ;
    const int r = bx % d.ctasPerZ;
    const int m0 = (r / d.ntiles) << 7;
    const int n0 = (r % d.ntiles) << 7;
    const int N = d.N, lda = d.lda, ldb = d.ldb, ldc = d.ldc;
    const float* A = d.A;
    const float* B = d.B;
    const int kstart = z * d.KC;
    int kend = kstart + d.KC; if (kend > d.K) kend = d.K;
    const int nb = (kend - kstart + 31) >> 5;

    const uint32_t smbase = smem_u32(sm);
    const int lr = tid >> 3, c16 = tid & 7;

    // fragment-load address precompute
    const int ahi = (lane >> 4) & 1;
    const int bhi = (lane >> 3) & 1;
    uint32_t aoff[4]; int asw[4];
    #pragma unroll
    for (int mt = 0; mt < 4; mt++) {
        int rr = wm * 64 + mt * 16 + (lane & 7) + (lane & 8);
        aoff[mt] = rr * 128;
        asw[mt] = rr & 7;
    }
    uint32_t boff[2]; int bsw[2];
    #pragma unroll
    for (int nn = 0; nn < 2; nn++) {
        int rr = wn * 32 + nn * 16 + (lane & 7) + ((lane & 16) >> 1);
        boff[nn] = 16384 + rr * 128;
        bsw[nn] = rr & 7;
    }

    float c[4][4][4];
    #pragma unroll
    for (int i = 0; i < 4; i++)
        #pragma unroll
        for (int j = 0; j < 4; j++)
            #pragma unroll
            for (int q = 0; q < 4; q++) c[i][j][q] = 0.f;

    // ---- prologue: fill stages 0,1 ----
    tmma_issue(smbase, 0, kstart, kend, A, lda, B, ldb, m0, n0, N, lr, c16);
    if (nb > 1)
        tmma_issue(smbase, 1, kstart + 32, kend, A, lda, B, ldb, m0, n0, N, lr, c16);
    else
        CP_COMMIT();

    for (int kb = 0; kb < nb; kb++) {
        CP_WAIT1();
        __syncthreads();
        const uint32_t sp = smbase + (kb % 3) * 32768;
        #pragma unroll
        for (int ks = 0; ks < 4; ks++) {
            uint32_t af[4][4], bf[4][2];
            #pragma unroll
            for (int mt = 0; mt < 4; mt++) {
                uint32_t ad = sp + aoff[mt] + ((((ks << 1) + ahi) ^ asw[mt]) << 4);
                LDSM4(af[mt][0], af[mt][1], af[mt][2], af[mt][3], ad);
            }
            #pragma unroll
            for (int nn = 0; nn < 2; nn++) {
                uint32_t r0, r1, r2, r3;
                uint32_t bd = sp + boff[nn] + ((((ks << 1) + bhi) ^ bsw[nn]) << 4);
                LDSM4(r0, r1, r2, r3, bd);
                bf[nn * 2][0] = r0; bf[nn * 2][1] = r1;
                bf[nn * 2 + 1][0] = r2; bf[nn * 2 + 1][1] = r3;
            }
            #pragma unroll
            for (int mt = 0; mt < 4; mt++)
                #pragma unroll
                for (int nt = 0; nt < 4; nt++)
                    mma_tf32(c[mt][nt], af[mt], bf[nt]);
        }
        const int nk = kb + 2;
        if (nk < nb)
            tmma_issue(smbase, nk % 3, kstart + nk * 32, kend,
                       A, lda, B, ldb, m0, n0, N, lr, c16);
        else
            CP_COMMIT();
    }

    // ---- epilogue ----
    const float* bias = d.bias;
    float* Cz = d.C + (size_t)z * d.zstride;
    #pragma unroll
    for (int mt = 0; mt < 4; mt++) {
        int r0 = m0 + wm * 64 + mt * 16 + gid;
        #pragma unroll
        for (int nt = 0; nt < 4; nt++) {
            int cc = n0 + wn * 32 + nt * 8 + 2 * tg;
            float* p0 = Cz + (size_t)r0 * ldc + cc;
            float* p1 = p0 + 8 * ldc;
            if (cc < N) {
                float bb = bias ? bias[cc] : 0.f;
                p0[0] = c[mt][nt][0] + bb;
                p1[0] = c[mt][nt][2] + bb;
            }
            if (cc + 1 < N) {
                float bb = bias ? bias[cc + 1] : 0.f;
                p0[1] = c[mt][nt][1] + bb;
                p1[1] = c[mt][nt][3] + bb;
            }
        }
    }
}

// ---------------- fused combine (et: 8 parts, no act | z1: 4 parts, tanh) ----------------
__global__ void combine2(const float* __restrict__ pa, const float* __restrict__ ba,
                         float* __restrict__ oa,
                         const float* __restrict__ pz, const float* __restrict__ bz,
                         float* __restrict__ oz)
{
    int blk = blockIdx.x;
    if (blk < 1024) {
        int i = blk * 256 + threadIdx.x;
        float v = ba[i & 511];
        #pragma unroll
        for (int j = 0; j < 8; j++) v += pa[i + (size_t)j * 262144];
        oa[i] = v;
    } else {
        int i = (blk - 1024) * 256 + threadIdx.x;
        float v = bz[i & 1023];
        #pragma unroll
        for (int j = 0; j < 4; j++) v += pz[i + (size_t)j * 524288];
        oz[i] = tanhf(v);
    }
}

// ---------------- K1: embedding + concat builders ----------------
__global__ void embed_kernel(const int* __restrict__ input,
                             const int* __restrict__ input_d,
                             const float* __restrict__ hidden,
                             const float* __restrict__ ans,
                             const float* __restrict__ emb_w,
                             const float* __restrict__ emb_d_w,
                             float* __restrict__ ahead,
                             float* __restrict__ minp)
{
    int b = blockIdx.x;
    int t = threadIdx.x;  // 128
    int tok = input[b];
    const float* src;
    if (tok > 2003) {
        int di = tok - 2004;
        if (di > LCC - 1) di = LCC - 1;
        if (di < 0) di = 0;
        int dt = input_d[b * LCC + di];
        src = emb_d_w + (size_t)dt * EE;
    } else {
        int tv = tok < 0 ? 0 : tok;
        src = emb_w + (size_t)tv * EE;
    }
    float* ah = ahead + (size_t)b * GRU_IN;
    float* mp = minp + (size_t)b * MLP_IN;
    for (int j = t; j < EE; j += 128) {
        float e = src[j];
        ah[512 + j] = e;
        mp[1536 + j] = e;
    }
    for (int h = t; h < HH; h += 128) {
        float hv = hidden[(size_t)b * HH + h];
        float av = ans[(size_t)b * HH + h];
        ah[h] = hv;
        ah[812 + h] = av;
        mp[1024 + h] = av;
    }
}

// ---------------- K3: reduce partials + bias, tanh, softmax (512 thr, 4-way s-split) ----
__global__ void attn_finalize(const float* __restrict__ partial,
                              const float* __restrict__ attn_b,
                              float* __restrict__ attnw)
{
    __shared__ float pacc[512];
    __shared__ float sred[4];
    int b = blockIdx.x, t = threadIdx.x;  // 512
    int g = t >> 7, l = t & 127;
    const float* pb = partial + (size_t)b * (NSPLIT * LCC);
    float acc = 0.f;
    if (l < LCC) {
        int s0 = g * 17;
        #pragma unroll
        for (int s = 0; s < 17; s++) acc += pb[(s0 + s) * LCC + l];
    }
    pacc[t] = acc;
    __syncthreads();
    if (t < 128) {
        float v = -1e30f;
        if (t < LCC)
            v = tanhf(attn_b[t] + pacc[t] + pacc[128 + t] + pacc[256 + t] + pacc[384 + t]);
        float m = warpReduceMax(v);
        if ((t & 31) == 0) sred[t >> 5] = m;
        __syncwarp();
        __syncthreads();
        m = fmaxf(fmaxf(sred[0], sred[1]), fmaxf(sred[2], sred[3]));
        float e = (t < LCC) ? __expf(v - m) : 0.f;
        float ss = warpReduceSum(e);
        __syncthreads();
        if ((t & 31) == 0) sred[t >> 5] = ss;
        __syncthreads();
        float tot = sred[0] + sred[1] + sred[2] + sred[3];
        if (t < LCC) attnw[(size_t)b * LCC + t] = e / tot;
    }
}

// ---------------- K4: c_t = einsum('bl,blh->bh') (float4) ----------------
__global__ void ct_kernel(const float* __restrict__ annot,
                          const float* __restrict__ attnw,
                          float* __restrict__ minp)
{
    int b = blockIdx.x, t = threadIdx.x;  // 128 -> 4 h each
    __shared__ float w[LCC];
    if (t < LCC) w[t] = attnw[(size_t)b * LCC + t];
    __syncthreads();
    const float4* Ab = (const float4*)(annot + (size_t)b * ANNOT_K);
    float ax = 0.f, ay = 0.f, az = 0.f, aw = 0.f;
    #pragma unroll 4
    for (int l = 0; l < LCC; l++) {
        float4 v = Ab[l * 128 + t];
        float wl = w[l];
        ax = fmaf(wl, v.x, ax); ay = fmaf(wl, v.y, ay);
        az = fmaf(wl, v.z, az); aw = fmaf(wl, v.w, aw);
    }
    *(float4*)(minp + (size_t)b * MLP_IN + 512 + 4 * t) = make_float4(ax, ay, az, aw);
}

// ---------------- K5: GRU elementwise (sums 2 split-K partials inline) ----------------
__global__ void gru_kernel(const float* __restrict__ giP,
                           const float* __restrict__ ghP,
                           const float* __restrict__ b_ih,
                           const float* __restrict__ b_hh,
                           const float* __restrict__ h0,
                           float* __restrict__ minp,
                           float* __restrict__ out0,
                           float* __restrict__ out1)
{
    int i = blockIdx.x * blockDim.x + threadIdx.x;  // 512*512
    int b = i >> 9, h = i & 511;
    size_t o = (size_t)b * 1536;
    const float* g0 = giP + o;
    const float* g1 = giP + 786432 + o;
    const float* q0 = ghP + o;
    const float* q1 = ghP + 786432 + o;
    float ir = g0[h] + g1[h] + b_ih[h];
    float iz = g0[512 + h] + g1[512 + h] + b_ih[512 + h];
    float in_ = g0[1024 + h] + g1[1024 + h] + b_ih[1024 + h];
    float hr = q0[h] + q1[h] + b_hh[h];
    float hz = q0[512 + h] + q1[512 + h] + b_hh[512 + h];
    float hn = q0[1024 + h] + q1[1024 + h] + b_hh[1024 + h];
    float r = 1.f / (1.f + __expf(-(ir + hr)));
    float z = 1.f / (1.f + __expf(-(iz + hz)));
    float n = tanhf(in_ + r * hn);
    float hnew = (1.f - z) * n + z * h0[i];
    minp[(size_t)b * MLP_IN + h] = hnew;
    out0[i] = hnew;
    out1[i] = hnew;
}

// ---------------- K6: z2 combine + z_t + output softmax + log, write p_t ----------------
__global__ void final_kernel(const float* __restrict__ olog,
                             const float* __restrict__ z2P,
                             const float* __restrict__ zt_b2,
                             const float* __restrict__ zt_W3,
                             const float* __restrict__ zt_b3,
                             const float* __restrict__ attnw,
                             float* __restrict__ pout)
{
    __shared__ float buf[OO];
    __shared__ float sred[16];
    __shared__ float sbc;
    int b = blockIdx.x, t = threadIdx.x;  // 512 threads, 16 warps

    // z2[h=t] = tanh(sum of 4 partials + b2), then z_t dot
    size_t o = (size_t)b * HH + t;
    float zv = z2P[o] + z2P[262144 + o] + z2P[524288 + o] + z2P[786432 + o] + zt_b2[t];
    zv = tanhf(zv);
    float s = zv * zt_W3[t];
    s = warpReduceSum(s);
    if ((t & 31) == 0) sred[t >> 5] = s;
    __syncthreads();
    if (t == 0) {
        float tot = 0.f;
        for (int w = 0; w < 16; w++) tot += sred[w];
        sbc = 1.f / (1.f + __expf(-(tot + zt_b3[0])));
    }
    __syncthreads();
    float zt = sbc;

    // logits -> smem + max
    const float* ob = olog + (size_t)b * OO;
    float mx = -1e30f;
    for (int j = t; j < OO; j += 512) {
        float v = ob[j];
        buf[j] = v;
        mx = fmaxf(mx, v);
    }
    mx = warpReduceMax(mx);
    __syncthreads();
    if ((t & 31) == 0) sred[t >> 5] = mx;
    __syncthreads();
    if (t == 0) {
        float mm = sred[0];
        for (int w = 1; w < 16; w++) mm = fmaxf(mm, sred[w]);
        sbc = mm;
    }
    __syncthreads();
    mx = sbc;

    float se = 0.f;
    for (int j = t; j < OO; j += 512) {
        float e = __expf(buf[j] - mx);
        buf[j] = e;
        se += e;
    }
    se = warpReduceSum(se);
    __syncthreads();
    if ((t & 31) == 0) sred[t >> 5] = se;
    __syncthreads();
    if (t == 0) {
        float tot = 0.f;
        for (int w = 0; w < 16; w++) tot += sred[w];
        sbc = tot;
    }
    __syncthreads();
    float cc = zt / sbc;

    float* pb = pout + (size_t)b * (OO + LCC);
    for (int j = t; j < OO; j += 512)
        pb[j] = __logf(buf[j] * cc + 1e-20f);
    float omz = 1.f - zt;
    for (int l = t; l < LCC; l += 512)
        pb[OO + l] = __logf(attnw[(size_t)b * LCC + l] * omz + 1e-20f);
}

// ---------------- launch ----------------
static GDesc mkdesc(const float* A, int lda, const float* B, int ldb,
                    const float* bias, float* C, int ldc,
                    int M, int N, int K, int KC, long zstride, int zcount)
{
    GDesc d;
    d.A = A; d.B = B; d.bias = bias; d.C = C;
    d.lda = lda; d.ldb = ldb; d.ldc = ldc;
    d.N = N; d.K = K; d.KC = KC; d.zstride = zstride;
    d.ntiles = (N + 127) / 128;
    d.ctasPerZ = (M / 128) * d.ntiles;
    d.nCtas = d.ctasPerZ * zcount;
    return d;
}

extern "C" void kernel_launch(void* const* d_in, const int* in_sizes, int n_in,
                              void* d_out, int out_size)
{
    const int*   input   = (const int*)d_in[0];
    const int*   input_d = (const int*)d_in[1];
    const float* hidden  = (const float*)d_in[2];
    const float* annot   = (const float*)d_in[3];
    const float* ans     = (const float*)d_in[4];
    const float* emb_w   = (const float*)d_in[5];
    const float* emb_d_w = (const float*)d_in[6];
    const float* attn_W  = (const float*)d_in[7];
    const float* attn_b  = (const float*)d_in[8];
    const float* W_ih    = (const float*)d_in[9];
    const float* W_hh    = (const float*)d_in[10];
    const float* b_ih    = (const float*)d_in[11];
    const float* b_hh    = (const float*)d_in[12];
    const float* mlp_W   = (const float*)d_in[13];
    const float* mlp_b   = (const float*)d_in[14];
    const float* out_W   = (const float*)d_in[15];
    const float* out_b   = (const float*)d_in[16];
    const float* zt_W1   = (const float*)d_in[17];
    const float* zt_b1   = (const float*)d_in[18];
    const float* zt_W2   = (const float*)d_in[19];
    const float* zt_b2   = (const float*)d_in[20];
    const float* zt_W3   = (const float*)d_in[21];
    const float* zt_b3   = (const float*)d_in[22];
    float* out = (float*)d_out;

    float* scr = nullptr;
    cudaGetSymbolAddress((void**)&scr, g_scratch);
    float* ahead = scr + OFF_AHEAD;
    float* minp  = scr + OFF_MINP;
    float* part  = scr + OFF_PART;
    float* attnw = scr + OFF_ATTNW;
    float* giP   = scr + OFF_GIP;
    float* ghP   = scr + OFF_GHP;
    float* etP   = scr + OFF_ETP;
    float* et    = scr + OFF_ET;
    float* ologs = scr + OFF_OLOG;
    float* z1P   = scr + OFF_Z1P;
    float* z1    = scr + OFF_Z1;
    float* z2P   = scr + OFF_Z2P;

    cudaFuncSetAttribute(tmma2, cudaFuncAttributeMaxDynamicSharedMemorySize, TMMA_SMEM);

    // 1. embedding + concat staging
    embed_kernel<<<BB, 128>>>(input, input_d, hidden, ans, emb_w, emb_d_w, ahead, minp);

    // 2. attention logits: annot (64 K-splits) + head (4 K-splits), one launch
    GDesc dAA = mkdesc(annot, ANNOT_K, attn_W + GRU_IN, ATTN_IN, nullptr,
                       part, NSPLIT * LCC, BB, LCC, ANNOT_K, 800, LCC, 64);
    GDesc dAH = mkdesc(ahead, GRU_IN, attn_W, ATTN_IN, nullptr,
                       part + 64 * LCC, NSPLIT * LCC, BB, LCC, GRU_IN, 332, LCC, 4);
    tmma2<<<dAA.nCtas + dAH.nCtas, 256, TMMA_SMEM>>>(dAA, dAH);
    attn_finalize<<<BB, 512>>>(part, attn_b, attnw);

    // 3. context vector
    ct_kernel<<<BB, 128>>>(annot, attnw, minp);

    // 4. GRU gates (gi + gh fused), then elementwise
    GDesc dGI = mkdesc(minp + 512, MLP_IN, W_ih, GRU_IN, nullptr,
                       giP, 1536, BB, 1536, GRU_IN, 664, 786432, 2);
    GDesc dGH = mkdesc(hidden, HH, W_hh, HH, nullptr,
                       ghP, 1536, BB, 1536, HH, 256, 786432, 2);
    tmma2<<<dGI.nCtas + dGH.nCtas, 256, TMMA_SMEM>>>(dGI, dGH);
    gru_kernel<<<1024, 256>>>(giP, ghP, b_ih, b_hh, hidden, minp, out, out + BB * HH);

    // 5. mlp + z1 fused, then fused combine
    GDesc dML = mkdesc(minp, MLP_IN, mlp_W, MLP_IN, nullptr,
                       etP, HH, BB, HH, MLP_IN, 256, 262144, 8);
    GDesc dZ1 = mkdesc(minp, MLP_IN, zt_W1, MLP_IN, nullptr,
                       z1P, 1024, BB, 1024, MLP_IN, 480, 524288, 4);
    tmma2<<<dML.nCtas + dZ1.nCtas, 256, TMMA_SMEM>>>(dML, dZ1);
    combine2<<<3072, 256>>>(etP, mlp_b, et, z1P, zt_b1, z1);

    // 6. output head + z2 fused
    GDesc dOU = mkdesc(et, HH, out_W, HH, out_b,
                       ologs, OO, BB, OO, HH, HH, 0, 1);
    GDesc dZ2 = mkdesc(z1, 1024, zt_W2, 1024, nullptr,
                       z2P, HH, BB, HH, 1024, 256, 262144, 4);
    tmma2<<<dOU.nCtas + dZ2.nCtas, 256, TMMA_SMEM>>>(dOU, dZ2);

    // 7. final: z2 combine + z_t + softmax/log + p_t
    final_kernel<<<BB, 512>>>(ologs, z2P, zt_b2, zt_W3, zt_b3, attnw, out + 2 * BB * HH);
}

// round 6
// speedup vs baseline: 6.2987x; 1.1702x over previous
#include <cuda_runtime.h>
#include <cuda_fp16.h>
#include <cstdint>
#include <math.h>

// ---------------- problem constants ----------------
#define BB 512
#define HH 512
#define EE 300
#define LCC 100
#define OO 2004
#define ANNOT_K 51200
#define NSPLIT 68          // 64 annot + 4 head splits

// padded fp16 row widths
#define AHEAD_LD 1328      // 1324 -> 1328
#define MINP_LD  1840      // 1836 -> 1840

// ---------------- fp32 scratch ----------------
#define OFF_PART  0UL                    // 512*6800
#define OFF_ATTNW 3481600UL              // 512*100
#define OFF_GIP   3532800UL              // 2*512*1536
#define OFF_GHP   5105664UL              // 2*512*1536
#define OFF_ETP   6678528UL              // 8*512*512
#define OFF_OLOG  8775680UL              // 512*2004
#define OFF_Z1P   9801728UL              // 4*512*1024
#define OFF_Z2P   11898880UL             // 4*512*512
#define F32_TOTAL 12947456UL

// ---------------- fp16 scratch ----------------
#define HOFF_ANNOT  0UL                  // 512*51200
#define HOFF_WANNOT 26214400UL           // 100*51200
#define HOFF_WHEAD  31334400UL           // 100*1328
#define HOFF_HIDDEN 31467200UL           // 512*512
#define HOFF_WIH    31729344UL           // 1536*1328
#define HOFF_WHH    33769152UL           // 1536*512
#define HOFF_MLPW   34555584UL           // 512*1840
#define HOFF_OUTW   35497664UL           // 2004*512
#define HOFF_Z1W    36523712UL           // 1024*1840
#define HOFF_Z2W    38407872UL           // 512*1024
#define HOFF_AHEAD  38932160UL           // 512*1328
#define HOFF_MINP   39612096UL           // 512*1840
#define HOFF_ET     40554176UL           // 512*512
#define HOFF_Z1     40816320UL           // 512*1024
#define F16_TOTAL   41340608UL

__device__ float g_f32[F32_TOTAL];
__device__ __align__(16) __half g_f16[F16_TOTAL];

// ---------------- low-level helpers ----------------
__device__ __forceinline__ uint32_t smem_u32(const void* p) {
    uint32_t a;
    asm("{ .reg .u64 t; cvta.to.shared.u64 t, %1; cvt.u32.u64 %0, t; }"
        : "=r"(a) : "l"(p));
    return a;
}
__device__ __forceinline__ void cpasync16(uint32_t dst, const void* src, int sz) {
    asm volatile("cp.async.cg.shared.global [%0], [%1], 16, %2;"
                 :: "r"(dst), "l"(src), "r"(sz) : "memory");
}
#define CP_COMMIT() asm volatile("cp.async.commit_group;" ::: "memory")
#define CP_WAIT1()  asm volatile("cp.async.wait_group 1;" ::: "memory")
#define LDSM4(r0, r1, r2, r3, addr) \
    asm volatile("ldmatrix.sync.aligned.m8n8.x4.shared.b16 {%0,%1,%2,%3}, [%4];" \
        : "=r"(r0), "=r"(r1), "=r"(r2), "=r"(r3) : "r"(addr))
__device__ __forceinline__ void mma_f16(float* c, const uint32_t* a, const uint32_t* b) {
    asm volatile(
        "mma.sync.aligned.m16n8k16.row.col.f32.f16.f16.f32 "
        "{%0,%1,%2,%3}, {%4,%5,%6,%7}, {%8,%9}, {%0,%1,%2,%3};"
        : "+f"(c[0]), "+f"(c[1]), "+f"(c[2]), "+f"(c[3])
        : "r"(a[0]), "r"(a[1]), "r"(a[2]), "r"(a[3]), "r"(b[0]), "r"(b[1]));
}
__device__ __forceinline__ float warpReduceSum(float v) {
    #pragma unroll
    for (int o = 16; o > 0; o >>= 1) v += __shfl_xor_sync(0xffffffffu, v, o);
    return v;
}
__device__ __forceinline__ float warpReduceMax(float v) {
    #pragma unroll
    for (int o = 16; o > 0; o >>= 1) v = fmaxf(v, __shfl_xor_sync(0xffffffffu, v, o));
    return v;
}

// ================= fp32 -> fp16 convert (padded, zero-filled) =================
struct ConvSegs {
    const float* src[10];
    __half* dst[10];
    int srcld[10], K[10], Kp[10];
    long start[11];
};

__global__ void conv_kernel(ConvSegs cs)
{
    long total = cs.start[10] >> 3;
    long stride = (long)gridDim.x * blockDim.x;
    for (long gidx = (long)blockIdx.x * blockDim.x + threadIdx.x; gidx < total; gidx += stride) {
        long e = gidx << 3;
        int s = 0;
        #pragma unroll
        for (int j = 0; j < 9; j++) if (e >= cs.start[j + 1]) s = j + 1;
        long loc = e - cs.start[s];
        int Kp = cs.Kp[s];
        long row = loc / Kp;
        int col = (int)(loc - row * Kp);
        const float* src = cs.src[s] + row * (long)cs.srcld[s] + col;
        int K = cs.K[s];
        __half2 h[4];
        if (col + 8 <= K) {
            float4 v0 = *(const float4*)src;
            float4 v1 = *(const float4*)(src + 4);
            h[0] = __floats2half2_rn(v0.x, v0.y);
            h[1] = __floats2half2_rn(v0.z, v0.w);
            h[2] = __floats2half2_rn(v1.x, v1.y);
            h[3] = __floats2half2_rn(v1.z, v1.w);
        } else {
            float t[8];
            #pragma unroll
            for (int j = 0; j < 8; j++) t[j] = (col + j < K) ? src[j] : 0.f;
            h[0] = __floats2half2_rn(t[0], t[1]);
            h[1] = __floats2half2_rn(t[2], t[3]);
            h[2] = __floats2half2_rn(t[4], t[5]);
            h[3] = __floats2half2_rn(t[6], t[7]);
        }
        *(uint4*)(cs.dst[s] + loc) = *(uint4*)h;
    }
}

// ================= descriptor-fused fp16 mma GEMM: C = A(M,K) @ B(N,K)^T ============
// BM=128, BN=128, BK=64 halfs (128B rows, XOR-8 16B swizzle), 8 warps (2m x 4n),
// warp tile 64x32, 3-stage cp.async, m16n8k16 HMMA, fp32 accum.
struct GDesc {
    const __half* A; const __half* B; const float* bias; float* C;
    int lda, ldb, ldc, N, K, KC;
    long zstride;
    int ntiles, ctasPerZ, nCtas;
};
#define TMMA_SMEM 98304   // 3 stages x (16KB A + 16KB B)

__device__ __forceinline__ void tmma_issue_h(
    uint32_t smbase, int p, int kk, int kend,
    const __half* A, int lda, const __half* B, int ldb,
    int m0, int n0, int N, int lr, int c16)
{
    const int kc = kk + (c16 << 3);
    const bool kok = (kc + 8 <= kend);
    const int szk = kok ? 16 : 0;
    #pragma unroll
    for (int i = 0; i < 4; i++) {
        int row = lr + (i << 5);
        const __half* src = kok ? (A + (size_t)(m0 + row) * lda + kc) : A;
        uint32_t dst = smbase + p * 32768 + row * 128 + ((c16 ^ (row & 7)) << 4);
        cpasync16(dst, src, szk);
    }
    #pragma unroll
    for (int i = 0; i < 4; i++) {
        int row = lr + (i << 5);
        int n = n0 + row;
        bool ok = kok && (n < N);
        int sz = ok ? 16 : 0;
        const __half* src = ok ? (B + (size_t)n * ldb + kc) : B;
        uint32_t dst = smbase + p * 32768 + 16384 + row * 128 + ((c16 ^ (row & 7)) << 4);
        cpasync16(dst, src, sz);
    }
    CP_COMMIT();
}

__global__ void __launch_bounds__(256, 2) tmma2h(GDesc d0, GDesc d1)
{
    extern __shared__ __align__(1024) uint32_t sm[];
    const int tid = threadIdx.x;
    const int lane = tid & 31, wid = tid >> 5;
    const int wm = wid & 1, wn = wid >> 1;
    const int gid = lane >> 2, tg = lane & 3;

    int bx = blockIdx.x;
    const GDesc& d = (bx < d0.nCtas) ? d0 : d1;
    if (bx >= d0.nCtas) bx -= d0.nCtas;
    const int z = bx / d.ctasPerZ;
    const int r = bx % d.ctasPerZ;
    const int m0 = (r / d.ntiles) << 7;
    const int n0 = (r % d.ntiles) << 7;
    const int N = d.N, lda = d.lda, ldb = d.ldb, ldc = d.ldc;
    const __half* A = d.A;
    const __half* B = d.B;
    const int kstart = z * d.KC;
    int kend = kstart + d.KC; if (kend > d.K) kend = d.K;
    const int nb = (kend - kstart + 63) >> 6;

    const uint32_t smbase = smem_u32(sm);
    const int lr = tid >> 3, c16 = tid & 7;

    // fragment address precompute
    const int ahi = lane >> 4;             // A k-chunk select (0/1)
    const int bhi = (lane >> 3) & 1;       // B k-chunk select
    uint32_t aoff[4]; int asw[4];
    #pragma unroll
    for (int mt = 0; mt < 4; mt++) {
        int rr = wm * 64 + mt * 16 + (lane & 15);
        aoff[mt] = rr * 128;
        asw[mt] = rr & 7;
    }
    uint32_t boff[2]; int bsw[2];
    #pragma unroll
    for (int nn = 0; nn < 2; nn++) {
        int rr = wn * 32 + nn * 16 + (lane & 7) + ((lane & 16) >> 1);
        boff[nn] = 16384 + rr * 128;
        bsw[nn] = rr & 7;
    }

    float c[4][4][4];
    #pragma unroll
    for (int i = 0; i < 4; i++)
        #pragma unroll
        for (int j = 0; j < 4; j++)
            #pragma unroll
            for (int q = 0; q < 4; q++) c[i][j][q] = 0.f;

    // prologue: fill stages 0,1
    tmma_issue_h(smbase, 0, kstart, kend, A, lda, B, ldb, m0, n0, N, lr, c16);
    if (nb > 1)
        tmma_issue_h(smbase, 1, kstart + 64, kend, A, lda, B, ldb, m0, n0, N, lr, c16);
    else
        CP_COMMIT();

    for (int kb = 0; kb < nb; kb++) {
        CP_WAIT1();
        __syncthreads();
        const uint32_t sp = smbase + (kb % 3) * 32768;
        #pragma unroll
        for (int ks = 0; ks < 4; ks++) {
            uint32_t af[4][4], bf[4][2];
            #pragma unroll
            for (int mt = 0; mt < 4; mt++) {
                uint32_t ad = sp + aoff[mt] + ((((ks << 1) + ahi) ^ asw[mt]) << 4);
                LDSM4(af[mt][0], af[mt][1], af[mt][2], af[mt][3], ad);
            }
            #pragma unroll
            for (int nn = 0; nn < 2; nn++) {
                uint32_t r0, r1, r2, r3;
                uint32_t bd = sp + boff[nn] + ((((ks << 1) + bhi) ^ bsw[nn]) << 4);
                LDSM4(r0, r1, r2, r3, bd);
                bf[nn * 2][0] = r0; bf[nn * 2][1] = r1;
                bf[nn * 2 + 1][0] = r2; bf[nn * 2 + 1][1] = r3;
            }
            #pragma unroll
            for (int mt = 0; mt < 4; mt++)
                #pragma unroll
                for (int nt = 0; nt < 4; nt++)
                    mma_f16(c[mt][nt], af[mt], bf[nt]);
        }
        const int nk = kb + 2;
        if (nk < nb)
            tmma_issue_h(smbase, nk % 3, kstart + nk * 64, kend,
                         A, lda, B, ldb, m0, n0, N, lr, c16);
        else
            CP_COMMIT();
    }

    // epilogue
    const float* bias = d.bias;
    float* Cz = d.C + (size_t)z * d.zstride;
    #pragma unroll
    for (int mt = 0; mt < 4; mt++) {
        int r0 = m0 + wm * 64 + mt * 16 + gid;
        #pragma unroll
        for (int nt = 0; nt < 4; nt++) {
            int cc = n0 + wn * 32 + nt * 8 + 2 * tg;
            float* p0 = Cz + (size_t)r0 * ldc + cc;
            float* p1 = p0 + 8 * ldc;
            if (cc < N) {
                float bb = bias ? bias[cc] : 0.f;
                p0[0] = c[mt][nt][0] + bb;
                p1[0] = c[mt][nt][2] + bb;
            }
            if (cc + 1 < N) {
                float bb = bias ? bias[cc + 1] : 0.f;
                p0[1] = c[mt][nt][1] + bb;
                p1[1] = c[mt][nt][3] + bb;
            }
        }
    }
}

// ---------------- fused combine (et: 8 parts | z1: 4 parts + tanh), fp16 out -------
__global__ void combine2(const float* __restrict__ pa, const float* __restrict__ ba,
                         __half* __restrict__ oa,
                         const float* __restrict__ pz, const float* __restrict__ bz,
                         __half* __restrict__ oz)
{
    int blk = blockIdx.x;
    if (blk < 1024) {
        int i = blk * 256 + threadIdx.x;
        float v = ba[i & 511];
        #pragma unroll
        for (int j = 0; j < 8; j++) v += pa[i + (size_t)j * 262144];
        oa[i] = __float2half_rn(v);
    } else {
        int i = (blk - 1024) * 256 + threadIdx.x;
        float v = bz[i & 1023];
        #pragma unroll
        for (int j = 0; j < 4; j++) v += pz[i + (size_t)j * 524288];
        oz[i] = __float2half_rn(tanhf(v));
    }
}

// ---------------- K1: embedding + fp16 concat staging ----------------
__global__ void embed_kernel(const int* __restrict__ input,
                             const int* __restrict__ input_d,
                             const float* __restrict__ hidden,
                             const float* __restrict__ ans,
                             const float* __restrict__ emb_w,
                             const float* __restrict__ emb_d_w,
                             __half* __restrict__ aheadH,
                             __half* __restrict__ minpH)
{
    int b = blockIdx.x;
    int t = threadIdx.x;  // 128
    int tok = input[b];
    const float* src;
    if (tok > 2003) {
        int di = tok - 2004;
        if (di > LCC - 1) di = LCC - 1;
        if (di < 0) di = 0;
        int dt = input_d[b * LCC + di];
        src = emb_d_w + (size_t)dt * EE;
    } else {
        int tv = tok < 0 ? 0 : tok;
        src = emb_w + (size_t)tv * EE;
    }
    __half* ah = aheadH + (size_t)b * AHEAD_LD;
    __half* mp = minpH + (size_t)b * MINP_LD;
    for (int j = t; j < EE; j += 128) {
        __half e = __float2half_rn(src[j]);
        ah[512 + j] = e;
        mp[1536 + j] = e;
    }
    for (int h = t; h < HH; h += 128) {
        __half hv = __float2half_rn(hidden[(size_t)b * HH + h]);
        __half av = __float2half_rn(ans[(size_t)b * HH + h]);
        ah[h] = hv;
        ah[812 + h] = av;
        mp[1024 + h] = av;
    }
    if (t < 4) {
        ah[1324 + t] = __float2half_rn(0.f);
        mp[1836 + t] = __float2half_rn(0.f);
    }
}

// ---------------- K3: partials reduce + tanh + softmax + fused c_t ----------------
__global__ void attn_finalize_ct(const float* __restrict__ partial,
                                 const float* __restrict__ attn_b,
                                 const __half* __restrict__ annotH,
                                 float* __restrict__ attnw,
                                 __half* __restrict__ minpH)
{
    __shared__ float pacc[512];
    __shared__ float sred[16];
    __shared__ float wsm[128];
    __shared__ float cacc[4096];
    int b = blockIdx.x, t = threadIdx.x;  // 512

    // phase A: reduce 68 split partials, 4-way over s
    {
        int g = t >> 7, l = t & 127;
        const float* pb = partial + (size_t)b * (NSPLIT * LCC);
        float acc = 0.f;
        if (l < LCC) {
            int s0 = g * 17;
            #pragma unroll
            for (int s = 0; s < 17; s++) acc += pb[(s0 + s) * LCC + l];
        }
        pacc[t] = acc;
    }
    __syncthreads();
    float v = -1e30f;
    if (t < LCC)
        v = tanhf(attn_b[t] + pacc[t] + pacc[128 + t] + pacc[256 + t] + pacc[384 + t]);
    float m = warpReduceMax(v);
    if ((t & 31) == 0) sred[t >> 5] = m;
    __syncthreads();
    float mm = sred[0];
    #pragma unroll
    for (int w = 1; w < 16; w++) mm = fmaxf(mm, sred[w]);
    float e = (t < LCC) ? __expf(v - mm) : 0.f;
    float ss = warpReduceSum(e);
    __syncthreads();
    if ((t & 31) == 0) sred[t >> 5] = ss;
    __syncthreads();
    float tot = 0.f;
    #pragma unroll
    for (int w = 0; w < 16; w++) tot += sred[w];
    if (t < LCC) {
        float wv = e / tot;
        attnw[(size_t)b * LCC + t] = wv;
        wsm[t] = wv;
    }
    __syncthreads();

    // phase B: c_t[h] = sum_l w[l] * annot[b,l,h] (fp16 annot, 8-way l-split)
    {
        int chunk = t & 63;    // 8 halfs each -> 512 h total
        int g2 = t >> 6;       // 0..7
        float acc8[8];
        #pragma unroll
        for (int j = 0; j < 8; j++) acc8[j] = 0.f;
        const __half* Ab = annotH + (size_t)b * ANNOT_K + chunk * 8;
        for (int l = g2; l < LCC; l += 8) {
            uint4 raw = *(const uint4*)(Ab + l * 512);
            float wl = wsm[l];
            const __half2* hp = (const __half2*)&raw;
            #pragma unroll
            for (int j = 0; j < 4; j++) {
                float2 f = __half22float2(hp[j]);
                acc8[2 * j]     = fmaf(wl, f.x, acc8[2 * j]);
                acc8[2 * j + 1] = fmaf(wl, f.y, acc8[2 * j + 1]);
            }
        }
        #pragma unroll
        for (int j = 0; j < 8; j++) cacc[g2 * 512 + chunk * 8 + j] = acc8[j];
    }
    __syncthreads();
    {
        float s = 0.f;
        #pragma unroll
        for (int g = 0; g < 8; g++) s += cacc[g * 512 + t];
        minpH[(size_t)b * MINP_LD + 512 + t] = __float2half_rn(s);
    }
}

// ---------------- K5: GRU elementwise (sums 2 split-K partials inline) -------------
__global__ void gru_kernel(const float* __restrict__ giP,
                           const float* __restrict__ ghP,
                           const float* __restrict__ b_ih,
                           const float* __restrict__ b_hh,
                           const float* __restrict__ h0,
                           __half* __restrict__ minpH,
                           float* __restrict__ out0,
                           float* __restrict__ out1)
{
    int i = blockIdx.x * blockDim.x + threadIdx.x;  // 512*512
    int b = i >> 9, h = i & 511;
    size_t o = (size_t)b * 1536;
    const float* g0 = giP + o;
    const float* g1 = giP + 786432 + o;
    const float* q0 = ghP + o;
    const float* q1 = ghP + 786432 + o;
    float ir = g0[h] + g1[h] + b_ih[h];
    float iz = g0[512 + h] + g1[512 + h] + b_ih[512 + h];
    float in_ = g0[1024 + h] + g1[1024 + h] + b_ih[1024 + h];
    float hr = q0[h] + q1[h] + b_hh[h];
    float hz = q0[512 + h] + q1[512 + h] + b_hh[512 + h];
    float hn = q0[1024 + h] + q1[1024 + h] + b_hh[1024 + h];
    float r = 1.f / (1.f + __expf(-(ir + hr)));
    float z = 1.f / (1.f + __expf(-(iz + hz)));
    float n = tanhf(in_ + r * hn);
    float hnew = (1.f - z) * n + z * h0[i];
    minpH[(size_t)b * MINP_LD + h] = __float2half_rn(hnew);
    out0[i] = hnew;
    out1[i] = hnew;
}

// ---------------- K6: z2 combine + z_t + output softmax + log, write p_t -----------
__global__ void final_kernel(const float* __restrict__ olog,
                             const float* __restrict__ z2P,
                             const float* __restrict__ zt_b2,
                             const float* __restrict__ zt_W3,
                             const float* __restrict__ zt_b3,
                             const float* __restrict__ attnw,
                             float* __restrict__ pout)
{
    __shared__ float buf[OO];
    __shared__ float sred[16];
    __shared__ float sbc;
    int b = blockIdx.x, t = threadIdx.x;  // 512 threads

    size_t o = (size_t)b * HH + t;
    float zv = z2P[o] + z2P[262144 + o] + z2P[524288 + o] + z2P[786432 + o] + zt_b2[t];
    zv = tanhf(zv);
    float s = zv * zt_W3[t];
    s = warpReduceSum(s);
    if ((t & 31) == 0) sred[t >> 5] = s;
    __syncthreads();
    if (t == 0) {
        float tot = 0.f;
        for (int w = 0; w < 16; w++) tot += sred[w];
        sbc = 1.f / (1.f + __expf(-(tot + zt_b3[0])));
    }
    __syncthreads();
    float zt = sbc;

    const float* ob = olog + (size_t)b * OO;
    float mx = -1e30f;
    for (int j = t; j < OO; j += 512) {
        float v = ob[j];
        buf[j] = v;
        mx = fmaxf(mx, v);
    }
    mx = warpReduceMax(mx);
    __syncthreads();
    if ((t & 31) == 0) sred[t >> 5] = mx;
    __syncthreads();
    if (t == 0) {
        float m2 = sred[0];
        for (int w = 1; w < 16; w++) m2 = fmaxf(m2, sred[w]);
        sbc = m2;
    }
    __syncthreads();
    mx = sbc;

    float se = 0.f;
    for (int j = t; j < OO; j += 512) {
        float e = __expf(buf[j] - mx);
        buf[j] = e;
        se += e;
    }
    se = warpReduceSum(se);
    __syncthreads();
    if ((t & 31) == 0) sred[t >> 5] = se;
    __syncthreads();
    if (t == 0) {
        float tot = 0.f;
        for (int w = 0; w < 16; w++) tot += sred[w];
        sbc = tot;
    }
    __syncthreads();
    float cc = zt / sbc;

    float* pb = pout + (size_t)b * (OO + LCC);
    for (int j = t; j < OO; j += 512)
        pb[j] = __logf(buf[j] * cc + 1e-20f);
    float omz = 1.f - zt;
    for (int l = t; l < LCC; l += 512)
        pb[OO + l] = __logf(attnw[(size_t)b * LCC + l] * omz + 1e-20f);
}

// ---------------- launch ----------------
static GDesc mkdesc(const __half* A, int lda, const __half* B, int ldb,
                    const float* bias, float* C, int ldc,
                    int M, int N, int K, int KC, long zstride, int zcount)
{
    GDesc d;
    d.A = A; d.B = B; d.bias = bias; d.C = C;
    d.lda = lda; d.ldb = ldb; d.ldc = ldc;
    d.N = N; d.K = K; d.KC = KC; d.zstride = zstride;
    d.ntiles = (N + 127) / 128;
    d.ctasPerZ = (M / 128) * d.ntiles;
    d.nCtas = d.ctasPerZ * zcount;
    return d;
}

extern "C" void kernel_launch(void* const* d_in, const int* in_sizes, int n_in,
                              void* d_out, int out_size)
{
    const int*   input   = (const int*)d_in[0];
    const int*   input_d = (const int*)d_in[1];
    const float* hidden  = (const float*)d_in[2];
    const float* annot   = (const float*)d_in[3];
    const float* ans     = (const float*)d_in[4];
    const float* emb_w   = (const float*)d_in[5];
    const float* emb_d_w = (const float*)d_in[6];
    const float* attn_W  = (const float*)d_in[7];
    const float* attn_b  = (const float*)d_in[8];
    const float* W_ih    = (const float*)d_in[9];
    const float* W_hh    = (const float*)d_in[10];
    const float* b_ih    = (const float*)d_in[11];
    const float* b_hh    = (const float*)d_in[12];
    const float* mlp_W   = (const float*)d_in[13];
    const float* mlp_b   = (const float*)d_in[14];
    const float* out_W   = (const float*)d_in[15];
    const float* out_b   = (const float*)d_in[16];
    const float* zt_W1   = (const float*)d_in[17];
    const float* zt_b1   = (const float*)d_in[18];
    const float* zt_W2   = (const float*)d_in[19];
    const float* zt_b2   = (const float*)d_in[20];
    const float* zt_W3   = (const float*)d_in[21];
    const float* zt_b3   = (const float*)d_in[22];
    float* out = (float*)d_out;

    float* f32 = nullptr;  __half* f16 = nullptr;
    cudaGetSymbolAddress((void**)&f32, g_f32);
    cudaGetSymbolAddress((void**)&f16, g_f16);

    float* part  = f32 + OFF_PART;
    float* attnw = f32 + OFF_ATTNW;
    float* giP   = f32 + OFF_GIP;
    float* ghP   = f32 + OFF_GHP;
    float* etP   = f32 + OFF_ETP;
    float* ologs = f32 + OFF_OLOG;
    float* z1P   = f32 + OFF_Z1P;
    float* z2P   = f32 + OFF_Z2P;

    __half* annotH  = f16 + HOFF_ANNOT;
    __half* WannotH = f16 + HOFF_WANNOT;
    __half* WheadH  = f16 + HOFF_WHEAD;
    __half* hiddenH = f16 + HOFF_HIDDEN;
    __half* WihH    = f16 + HOFF_WIH;
    __half* WhhH    = f16 + HOFF_WHH;
    __half* mlpWH   = f16 + HOFF_MLPW;
    __half* outWH   = f16 + HOFF_OUTW;
    __half* z1WH    = f16 + HOFF_Z1W;
    __half* z2WH    = f16 + HOFF_Z2W;
    __half* aheadH  = f16 + HOFF_AHEAD;
    __half* minpH   = f16 + HOFF_MINP;
    __half* etH     = f16 + HOFF_ET;
    __half* z1H     = f16 + HOFF_Z1;

    cudaFuncSetAttribute(tmma2h, cudaFuncAttributeMaxDynamicSharedMemorySize, TMMA_SMEM);

    // 0. convert weights + annot + hidden to fp16 (padded, zero-filled)
    ConvSegs cs;
    const float* srcs[10] = {annot, attn_W + 1324, attn_W, hidden, W_ih,
                             W_hh, mlp_W, out_W, zt_W1, zt_W2};
    __half* dsts[10] = {annotH, WannotH, WheadH, hiddenH, WihH,
                        WhhH, mlpWH, outWH, z1WH, z2WH};
    int slds[10] = {51200, 52524, 52524, 512, 1324, 512, 1836, 512, 1836, 1024};
    int Ks[10]   = {51200, 51200, 1324, 512, 1324, 512, 1836, 512, 1836, 1024};
    int Kps[10]  = {51200, 51200, 1328, 512, 1328, 512, 1840, 512, 1840, 1024};
    long rows[10] = {512, 100, 100, 512, 1536, 1536, 512, 2004, 1024, 512};
    long acc = 0;
    for (int i = 0; i < 10; i++) {
        cs.src[i] = srcs[i]; cs.dst[i] = dsts[i];
        cs.srcld[i] = slds[i]; cs.K[i] = Ks[i]; cs.Kp[i] = Kps[i];
        cs.start[i] = acc;
        acc += rows[i] * Kps[i];
    }
    cs.start[10] = acc;
    conv_kernel<<<4096, 256>>>(cs);

    // 1. embedding + fp16 concat staging
    embed_kernel<<<BB, 128>>>(input, input_d, hidden, ans, emb_w, emb_d_w, aheadH, minpH);

    // 2. attention logits: annot (64 K-splits) + head (4 K-splits), one launch
    GDesc dAA = mkdesc(annotH, ANNOT_K, WannotH, ANNOT_K, nullptr,
                       part, NSPLIT * LCC, BB, LCC, ANNOT_K, 800, LCC, 64);
    GDesc dAH = mkdesc(aheadH, AHEAD_LD, WheadH, AHEAD_LD, nullptr,
                       part + 64 * LCC, NSPLIT * LCC, BB, LCC, AHEAD_LD, 336, LCC, 4);
    tmma2h<<<dAA.nCtas + dAH.nCtas, 256, TMMA_SMEM>>>(dAA, dAH);

    // 3. finalize + fused c_t
    attn_finalize_ct<<<BB, 512>>>(part, attn_b, annotH, attnw, minpH);

    // 4. GRU gates (gi + gh fused), then elementwise
    GDesc dGI = mkdesc(minpH + 512, MINP_LD, WihH, AHEAD_LD, nullptr,
                       giP, 1536, BB, 1536, AHEAD_LD, 664, 786432, 2);
    GDesc dGH = mkdesc(hiddenH, HH, WhhH, HH, nullptr,
                       ghP, 1536, BB, 1536, HH, 256, 786432, 2);
    tmma2h<<<dGI.nCtas + dGH.nCtas, 256, TMMA_SMEM>>>(dGI, dGH);
    gru_kernel<<<1024, 256>>>(giP, ghP, b_ih, b_hh, hidden, minpH, out, out + BB * HH);

    // 5. mlp + z1 fused, then fused combine (fp16 outputs)
    GDesc dML = mkdesc(minpH, MINP_LD, mlpWH, MINP_LD, nullptr,
                       etP, HH, BB, HH, MINP_LD, 232, 262144, 8);
    GDesc dZ1 = mkdesc(minpH, MINP_LD, z1WH, MINP_LD, nullptr,
                       z1P, 1024, BB, 1024, MINP_LD, 464, 524288, 4);
    tmma2h<<<dML.nCtas + dZ1.nCtas, 256, TMMA_SMEM>>>(dML, dZ1);
    combine2<<<3072, 256>>>(etP, mlp_b, etH, z1P, zt_b1, z1H);

    // 6. output head + z2 fused
    GDesc dOU = mkdesc(etH, HH, outWH, HH, out_b,
                       ologs, OO, BB, OO, HH, HH, 0, 1);
    GDesc dZ2 = mkdesc(z1H, 1024, z2WH, 1024, nullptr,
                       z2P, HH, BB, HH, 1024, 256, 262144, 4);
    tmma2h<<<dOU.nCtas + dZ2.nCtas, 256, TMMA_SMEM>>>(dOU, dZ2);

    // 7. final: z2 combine + z_t + softmax/log + p_t
    final_kernel<<<BB, 512>>>(ologs, z2P, zt_b2, zt_W3, zt_b3, attnw, out + 2 * BB * HH);
}

// round 7
// speedup vs baseline: 6.3185x; 1.0032x over previous
#include <cuda_runtime.h>
#include <cuda_fp16.h>
#include <cstdint>
#include <math.h>

// ---------------- problem constants ----------------
#define BB 512
#define HH 512
#define EE 300
#define LCC 100
#define OO 2004
#define ANNOT_K 51200
#define NSPLIT 68          // 64 annot + 4 head splits
#define AHEAD_K 1324
#define MINP_LD 1840       // fp16 minp row: [h_new|c_t|ans|emb|pad4]
#define WIH_LD  1328       // 1324 padded

// ---------------- fp32 scratch ----------------
#define OFF_PART   0UL                   // 512*6800
#define OFF_ATTNW  3481600UL             // 512*100
#define OFF_GIP    3532800UL             // 3*512*1536
#define OFF_GH     5892096UL             // 512*1536
#define OFF_ETP    6678528UL             // 8*512*512
#define OFF_OLOGP  8775680UL             // 2*512*2004
#define OFF_Z1P    10827776UL            // 4*512*1024
#define OFF_Z2P    12924928UL            // 4*512*512
#define OFF_AHEAD  13973504UL            // 512*1324
#define F32_TOTAL  14651392UL

// ---------------- fp16 scratch ----------------
#define HOFF_WIH   0UL                   // 1536*1328
#define HOFF_MLPW  2039808UL             // 512*1840
#define HOFF_OUTW  2981888UL             // 2004*512
#define HOFF_Z1W   4007936UL             // 1024*1840
#define HOFF_Z2W   5892096UL             // 512*1024
#define HOFF_MINP  6416384UL             // 512*1840
#define HOFF_ET    7358464UL             // 512*512
#define HOFF_Z1    7620608UL             // 512*1024
#define F16_TOTAL  8144896UL

__device__ float g_f32[F32_TOTAL];
__device__ __align__(16) __half g_f16[F16_TOTAL];

// ---------------- low-level helpers ----------------
__device__ __forceinline__ uint32_t smem_u32(const void* p) {
    uint32_t a;
    asm("{ .reg .u64 t; cvta.to.shared.u64 t, %1; cvt.u32.u64 %0, t; }"
        : "=r"(a) : "l"(p));
    return a;
}
__device__ __forceinline__ void cpasync16(uint32_t dst, const void* src, int sz) {
    asm volatile("cp.async.cg.shared.global [%0], [%1], 16, %2;"
                 :: "r"(dst), "l"(src), "r"(sz) : "memory");
}
#define CP_COMMIT() asm volatile("cp.async.commit_group;" ::: "memory")
#define CP_WAIT1()  asm volatile("cp.async.wait_group 1;" ::: "memory")
#define LDSM4(r0, r1, r2, r3, addr) \
    asm volatile("ldmatrix.sync.aligned.m8n8.x4.shared.b16 {%0,%1,%2,%3}, [%4];" \
        : "=r"(r0), "=r"(r1), "=r"(r2), "=r"(r3) : "r"(addr))
__device__ __forceinline__ void mma_f16(float* c, const uint32_t* a, const uint32_t* b) {
    asm volatile(
        "mma.sync.aligned.m16n8k16.row.col.f32.f16.f16.f32 "
        "{%0,%1,%2,%3}, {%4,%5,%6,%7}, {%8,%9}, {%0,%1,%2,%3};"
        : "+f"(c[0]), "+f"(c[1]), "+f"(c[2]), "+f"(c[3])
        : "r"(a[0]), "r"(a[1]), "r"(a[2]), "r"(a[3]), "r"(b[0]), "r"(b[1]));
}
__device__ __forceinline__ void mma_tf32(float* c, const uint32_t* a, const uint32_t* b) {
    asm volatile(
        "mma.sync.aligned.m16n8k8.row.col.f32.tf32.tf32.f32 "
        "{%0,%1,%2,%3}, {%4,%5,%6,%7}, {%8,%9}, {%0,%1,%2,%3};"
        : "+f"(c[0]), "+f"(c[1]), "+f"(c[2]), "+f"(c[3])
        : "r"(a[0]), "r"(a[1]), "r"(a[2]), "r"(a[3]), "r"(b[0]), "r"(b[1]));
}
__device__ __forceinline__ float warpReduceSum(float v) {
    #pragma unroll
    for (int o = 16; o > 0; o >>= 1) v += __shfl_xor_sync(0xffffffffu, v, o);
    return v;
}
__device__ __forceinline__ float warpReduceMax(float v) {
    #pragma unroll
    for (int o = 16; o > 0; o >>= 1) v = fmaxf(v, __shfl_xor_sync(0xffffffffu, v, o));
    return v;
}

// ---------------- generic GEMM descriptor ----------------
struct GDesc {
    const void* A; const void* B; const float* bias; float* C;
    int lda, ldb, ldc, N, K, KC;
    long zstride;
    int ntiles, ctasPerZ, nCtas;
};
#define TMMA_SMEM 98304

// ================= tf32 GEMM (fp32 inputs): C = A(M,K) @ B(N,K)^T =================
// BM=128, BN=128, BK=32 floats (128B rows, XOR-8 16B swizzle), 8 warps (2m x 4n),
// warp tile 64x32, 3-stage cp.async. Three fused descriptors.
__device__ __forceinline__ void tmma_issue_f(
    uint32_t smbase, int p, int kk, int kend,
    const float* A, int lda, const float* B, int ldb,
    int m0, int n0, int N, int lr, int c16)
{
    const int kc = kk + (c16 << 2);
    const bool kok = (kc + 4 <= kend);
    const int szk = kok ? 16 : 0;
    #pragma unroll
    for (int i = 0; i < 4; i++) {
        int row = lr + (i << 5);
        const float* src = kok ? (A + (size_t)(m0 + row) * lda + kc) : A;
        uint32_t dst = smbase + p * 32768 + row * 128 + ((c16 ^ (row & 7)) << 4);
        cpasync16(dst, src, szk);
    }
    #pragma unroll
    for (int i = 0; i < 4; i++) {
        int row = lr + (i << 5);
        int n = n0 + row;
        bool ok = kok && (n < N);
        int sz = ok ? 16 : 0;
        const float* src = ok ? (B + (size_t)n * ldb + kc) : B;
        uint32_t dst = smbase + p * 32768 + 16384 + row * 128 + ((c16 ^ (row & 7)) << 4);
        cpasync16(dst, src, sz);
    }
    CP_COMMIT();
}

__global__ void __launch_bounds__(256, 2) tmma3f(GDesc d0, GDesc d1, GDesc d2)
{
    extern __shared__ __align__(1024) uint32_t sm[];
    const int tid = threadIdx.x;
    const int lane = tid & 31, wid = tid >> 5;
    const int wm = wid & 1, wn = wid >> 1;
    const int gid = lane >> 2, tg = lane & 3;

    int bx = blockIdx.x;
    const GDesc& d = (bx < d0.nCtas) ? d0 : ((bx < d0.nCtas + d1.nCtas) ? d1 : d2);
    if (bx >= d0.nCtas) bx -= d0.nCtas;
    if (&d == &d2) bx -= d1.nCtas;
    const int z = bx / d.ctasPerZ;
    const int r = bx % d.ctasPerZ;
    const int m0 = (r / d.ntiles) << 7;
    const int n0 = (r % d.ntiles) << 7;
    const int N = d.N, lda = d.lda, ldb = d.ldb, ldc = d.ldc;
    const float* A = (const float*)d.A;
    const float* B = (const float*)d.B;
    const int kstart = z * d.KC;
    int kend = kstart + d.KC; if (kend > d.K) kend = d.K;
    const int nb = (kend - kstart + 31) >> 5;

    const uint32_t smbase = smem_u32(sm);
    const int lr = tid >> 3, c16 = tid & 7;

    const int ahi = (lane >> 4) & 1;
    const int bhi = (lane >> 3) & 1;
    uint32_t aoff[4]; int asw[4];
    #pragma unroll
    for (int mt = 0; mt < 4; mt++) {
        int rr = wm * 64 + mt * 16 + (lane & 7) + (lane & 8);
        aoff[mt] = rr * 128;
        asw[mt] = rr & 7;
    }
    uint32_t boff[2]; int bsw[2];
    #pragma unroll
    for (int nn = 0; nn < 2; nn++) {
        int rr = wn * 32 + nn * 16 + (lane & 7) + ((lane & 16) >> 1);
        boff[nn] = 16384 + rr * 128;
        bsw[nn] = rr & 7;
    }

    float c[4][4][4];
    #pragma unroll
    for (int i = 0; i < 4; i++)
        #pragma unroll
        for (int j = 0; j < 4; j++)
            #pragma unroll
            for (int q = 0; q < 4; q++) c[i][j][q] = 0.f;

    tmma_issue_f(smbase, 0, kstart, kend, A, lda, B, ldb, m0, n0, N, lr, c16);
    if (nb > 1)
        tmma_issue_f(smbase, 1, kstart + 32, kend, A, lda, B, ldb, m0, n0, N, lr, c16);
    else
        CP_COMMIT();

    for (int kb = 0; kb < nb; kb++) {
        CP_WAIT1();
        __syncthreads();
        const uint32_t sp = smbase + (kb % 3) * 32768;
        #pragma unroll
        for (int ks = 0; ks < 4; ks++) {
            uint32_t af[4][4], bf[4][2];
            #pragma unroll
            for (int mt = 0; mt < 4; mt++) {
                uint32_t ad = sp + aoff[mt] + ((((ks << 1) + ahi) ^ asw[mt]) << 4);
                LDSM4(af[mt][0], af[mt][1], af[mt][2], af[mt][3], ad);
            }
            #pragma unroll
            for (int nn = 0; nn < 2; nn++) {
                uint32_t r0, r1, r2, r3;
                uint32_t bd = sp + boff[nn] + ((((ks << 1) + bhi) ^ bsw[nn]) << 4);
                LDSM4(r0, r1, r2, r3, bd);
                bf[nn * 2][0] = r0; bf[nn * 2][1] = r1;
                bf[nn * 2 + 1][0] = r2; bf[nn * 2 + 1][1] = r3;
            }
            #pragma unroll
            for (int mt = 0; mt < 4; mt++)
                #pragma unroll
                for (int nt = 0; nt < 4; nt++)
                    mma_tf32(c[mt][nt], af[mt], bf[nt]);
        }
        const int nk = kb + 2;
        if (nk < nb)
            tmma_issue_f(smbase, nk % 3, kstart + nk * 32, kend,
                         A, lda, B, ldb, m0, n0, N, lr, c16);
        else
            CP_COMMIT();
    }

    const float* bias = d.bias;
    float* Cz = d.C + (size_t)z * d.zstride;
    #pragma unroll
    for (int mt = 0; mt < 4; mt++) {
        int r0 = m0 + wm * 64 + mt * 16 + gid;
        #pragma unroll
        for (int nt = 0; nt < 4; nt++) {
            int cc = n0 + wn * 32 + nt * 8 + 2 * tg;
            float* p0 = Cz + (size_t)r0 * ldc + cc;
            float* p1 = p0 + 8 * ldc;
            if (cc < N) {
                float bb = bias ? bias[cc] : 0.f;
                p0[0] = c[mt][nt][0] + bb;
                p1[0] = c[mt][nt][2] + bb;
            }
            if (cc + 1 < N) {
                float bb = bias ? bias[cc + 1] : 0.f;
                p0[1] = c[mt][nt][1] + bb;
                p1[1] = c[mt][nt][3] + bb;
            }
        }
    }
}

// ================= fp16 GEMM: C = A(M,K) @ B(N,K)^T, BK=64 halfs ================
__device__ __forceinline__ void tmma_issue_h(
    uint32_t smbase, int p, int kk, int kend,
    const __half* A, int lda, const __half* B, int ldb,
    int m0, int n0, int N, int lr, int c16)
{
    const int kc = kk + (c16 << 3);
    const bool kok = (kc + 8 <= kend);
    const int szk = kok ? 16 : 0;
    #pragma unroll
    for (int i = 0; i < 4; i++) {
        int row = lr + (i << 5);
        const __half* src = kok ? (A + (size_t)(m0 + row) * lda + kc) : A;
        uint32_t dst = smbase + p * 32768 + row * 128 + ((c16 ^ (row & 7)) << 4);
        cpasync16(dst, src, szk);
    }
    #pragma unroll
    for (int i = 0; i < 4; i++) {
        int row = lr + (i << 5);
        int n = n0 + row;
        bool ok = kok && (n < N);
        int sz = ok ? 16 : 0;
        const __half* src = ok ? (B + (size_t)n * ldb + kc) : B;
        uint32_t dst = smbase + p * 32768 + 16384 + row * 128 + ((c16 ^ (row & 7)) << 4);
        cpasync16(dst, src, sz);
    }
    CP_COMMIT();
}

__global__ void __launch_bounds__(256, 2) tmma2h(GDesc d0, GDesc d1)
{
    extern __shared__ __align__(1024) uint32_t sm[];
    const int tid = threadIdx.x;
    const int lane = tid & 31, wid = tid >> 5;
    const int wm = wid & 1, wn = wid >> 1;
    const int gid = lane >> 2, tg = lane & 3;

    int bx = blockIdx.x;
    const GDesc& d = (bx < d0.nCtas) ? d0 : d1;
    if (bx >= d0.nCtas) bx -= d0.nCtas;
    const int z = bx / d.ctasPerZ;
    const int r = bx % d.ctasPerZ;
    const int m0 = (r / d.ntiles) << 7;
    const int n0 = (r % d.ntiles) << 7;
    const int N = d.N, lda = d.lda, ldb = d.ldb, ldc = d.ldc;
    const __half* A = (const __half*)d.A;
    const __half* B = (const __half*)d.B;
    const int kstart = z * d.KC;
    int kend = kstart + d.KC; if (kend > d.K) kend = d.K;
    const int nb = (kend - kstart + 63) >> 6;

    const uint32_t smbase = smem_u32(sm);
    const int lr = tid >> 3, c16 = tid & 7;

    const int ahi = lane >> 4;
    const int bhi = (lane >> 3) & 1;
    uint32_t aoff[4]; int asw[4];
    #pragma unroll
    for (int mt = 0; mt < 4; mt++) {
        int rr = wm * 64 + mt * 16 + (lane & 15);
        aoff[mt] = rr * 128;
        asw[mt] = rr & 7;
    }
    uint32_t boff[2]; int bsw[2];
    #pragma unroll
    for (int nn = 0; nn < 2; nn++) {
        int rr = wn * 32 + nn * 16 + (lane & 7) + ((lane & 16) >> 1);
        boff[nn] = 16384 + rr * 128;
        bsw[nn] = rr & 7;
    }

    float c[4][4][4];
    #pragma unroll
    for (int i = 0; i < 4; i++)
        #pragma unroll
        for (int j = 0; j < 4; j++)
            #pragma unroll
            for (int q = 0; q < 4; q++) c[i][j][q] = 0.f;

    tmma_issue_h(smbase, 0, kstart, kend, A, lda, B, ldb, m0, n0, N, lr, c16);
    if (nb > 1)
        tmma_issue_h(smbase, 1, kstart + 64, kend, A, lda, B, ldb, m0, n0, N, lr, c16);
    else
        CP_COMMIT();

    for (int kb = 0; kb < nb; kb++) {
        CP_WAIT1();
        __syncthreads();
        const uint32_t sp = smbase + (kb % 3) * 32768;
        #pragma unroll
        for (int ks = 0; ks < 4; ks++) {
            uint32_t af[4][4], bf[4][2];
            #pragma unroll
            for (int mt = 0; mt < 4; mt++) {
                uint32_t ad = sp + aoff[mt] + ((((ks << 1) + ahi) ^ asw[mt]) << 4);
                LDSM4(af[mt][0], af[mt][1], af[mt][2], af[mt][3], ad);
            }
            #pragma unroll
            for (int nn = 0; nn < 2; nn++) {
                uint32_t r0, r1, r2, r3;
                uint32_t bd = sp + boff[nn] + ((((ks << 1) + bhi) ^ bsw[nn]) << 4);
                LDSM4(r0, r1, r2, r3, bd);
                bf[nn * 2][0] = r0; bf[nn * 2][1] = r1;
                bf[nn * 2 + 1][0] = r2; bf[nn * 2 + 1][1] = r3;
            }
            #pragma unroll
            for (int mt = 0; mt < 4; mt++)
                #pragma unroll
                for (int nt = 0; nt < 4; nt++)
                    mma_f16(c[mt][nt], af[mt], bf[nt]);
        }
        const int nk = kb + 2;
        if (nk < nb)
            tmma_issue_h(smbase, nk % 3, kstart + nk * 64, kend,
                         A, lda, B, ldb, m0, n0, N, lr, c16);
        else
            CP_COMMIT();
    }

    const float* bias = d.bias;
    float* Cz = d.C + (size_t)z * d.zstride;
    #pragma unroll
    for (int mt = 0; mt < 4; mt++) {
        int r0 = m0 + wm * 64 + mt * 16 + gid;
        #pragma unroll
        for (int nt = 0; nt < 4; nt++) {
            int cc = n0 + wn * 32 + nt * 8 + 2 * tg;
            float* p0 = Cz + (size_t)r0 * ldc + cc;
            float* p1 = p0 + 8 * ldc;
            if (cc < N) {
                float bb = bias ? bias[cc] : 0.f;
                p0[0] = c[mt][nt][0] + bb;
                p1[0] = c[mt][nt][2] + bb;
            }
            if (cc + 1 < N) {
                float bb = bias ? bias[cc + 1] : 0.f;
                p0[1] = c[mt][nt][1] + bb;
                p1[1] = c[mt][nt][3] + bb;
            }
        }
    }
}

// ================= fp32 -> fp16 weight convert (5 segments, padded) =================
struct ConvSegs {
    const float* src[5];
    __half* dst[5];
    int srcld[5], K[5], Kp[5];
    long start[6];
};

__global__ void conv_kernel(ConvSegs cs)
{
    long total = cs.start[5] >> 3;
    long stride = (long)gridDim.x * blockDim.x;
    for (long gidx = (long)blockIdx.x * blockDim.x + threadIdx.x; gidx < total; gidx += stride) {
        long e = gidx << 3;
        int s = 0;
        #pragma unroll
        for (int j = 0; j < 4; j++) if (e >= cs.start[j + 1]) s = j + 1;
        long loc = e - cs.start[s];
        int Kp = cs.Kp[s];
        long row = loc / Kp;
        int col = (int)(loc - row * Kp);
        const float* src = cs.src[s] + row * (long)cs.srcld[s] + col;
        int K = cs.K[s];
        __half2 h[4];
        if (col + 8 <= K) {
            float4 v0 = *(const float4*)src;
            float4 v1 = *(const float4*)(src + 4);
            h[0] = __floats2half2_rn(v0.x, v0.y);
            h[1] = __floats2half2_rn(v0.z, v0.w);
            h[2] = __floats2half2_rn(v1.x, v1.y);
            h[3] = __floats2half2_rn(v1.z, v1.w);
        } else {
            float t[8];
            #pragma unroll
            for (int j = 0; j < 8; j++) t[j] = (col + j < K) ? src[j] : 0.f;
            h[0] = __floats2half2_rn(t[0], t[1]);
            h[1] = __floats2half2_rn(t[2], t[3]);
            h[2] = __floats2half2_rn(t[4], t[5]);
            h[3] = __floats2half2_rn(t[6], t[7]);
        }
        *(uint4*)(cs.dst[s] + loc) = *(uint4*)h;
    }
}

// ---------------- K1: embedding + staging (fp32 ahead, fp16 minp) ----------------
__global__ void embed_kernel(const int* __restrict__ input,
                             const int* __restrict__ input_d,
                             const float* __restrict__ hidden,
                             const float* __restrict__ ans,
                             const float* __restrict__ emb_w,
                             const float* __restrict__ emb_d_w,
                             float* __restrict__ aheadF,
                             __half* __restrict__ minpH)
{
    int b = blockIdx.x;
    int t = threadIdx.x;  // 128
    int tok = input[b];
    const float* src;
    if (tok > 2003) {
        int di = tok - 2004;
        if (di > LCC - 1) di = LCC - 1;
        if (di < 0) di = 0;
        int dt = input_d[b * LCC + di];
        src = emb_d_w + (size_t)dt * EE;
    } else {
        int tv = tok < 0 ? 0 : tok;
        src = emb_w + (size_t)tv * EE;
    }
    float* ah = aheadF + (size_t)b * AHEAD_K;
    __half* mp = minpH + (size_t)b * MINP_LD;
    for (int j = t; j < EE; j += 128) {
        float e = src[j];
        ah[512 + j] = e;
        mp[1536 + j] = __float2half_rn(e);
    }
    for (int h = t; h < HH; h += 128) {
        float hv = hidden[(size_t)b * HH + h];
        float av = ans[(size_t)b * HH + h];
        ah[h] = hv;
        ah[812 + h] = av;
        mp[1024 + h] = __float2half_rn(av);
    }
    if (t < 4) mp[1836 + t] = __float2half_rn(0.f);
}

// ---------------- K3: partials reduce + tanh + softmax + fused c_t (fp32 annot) ----
__global__ void attn_finalize_ct(const float* __restrict__ partial,
                                 const float* __restrict__ attn_b,
                                 const float* __restrict__ annot,
                                 float* __restrict__ attnw,
                                 __half* __restrict__ minpH)
{
    __shared__ float pacc[512];
    __shared__ float sred[16];
    __shared__ float wsm[128];
    __shared__ float cacc[2048];
    int b = blockIdx.x, t = threadIdx.x;  // 512

    // phase A: reduce 68 split partials
    {
        int g = t >> 7, l = t & 127;
        const float* pb = partial + (size_t)b * (NSPLIT * LCC);
        float acc = 0.f;
        if (l < LCC) {
            int s0 = g * 17;
            #pragma unroll
            for (int s = 0; s < 17; s++) acc += pb[(s0 + s) * LCC + l];
        }
        pacc[t] = acc;
    }
    __syncthreads();
    float v = -1e30f;
    if (t < LCC)
        v = tanhf(attn_b[t] + pacc[t] + pacc[128 + t] + pacc[256 + t] + pacc[384 + t]);
    float m = warpReduceMax(v);
    if ((t & 31) == 0) sred[t >> 5] = m;
    __syncthreads();
    float mm = sred[0];
    #pragma unroll
    for (int w = 1; w < 16; w++) mm = fmaxf(mm, sred[w]);
    float e = (t < LCC) ? __expf(v - mm) : 0.f;
    float ss = warpReduceSum(e);
    __syncthreads();
    if ((t & 31) == 0) sred[t >> 5] = ss;
    __syncthreads();
    float tot = 0.f;
    #pragma unroll
    for (int w = 0; w < 16; w++) tot += sred[w];
    if (t < LCC) {
        float wv = e / tot;
        attnw[(size_t)b * LCC + t] = wv;
        wsm[t] = wv;
    }
    __syncthreads();

    // phase B: c_t[h] = sum_l w[l]*annot[b,l,h], fp32, 4 l-groups x 128 h-chunks
    {
        int hc = t & 127;       // float4 chunk -> h = 4*hc
        int g2 = t >> 7;        // 0..3, l in [25*g2, 25*g2+25)
        const float4* Ab = (const float4*)(annot + (size_t)b * ANNOT_K) + hc;
        float ax = 0.f, ay = 0.f, az = 0.f, aw = 0.f;
        float bx2 = 0.f, by2 = 0.f, bz2 = 0.f, bw2 = 0.f;
        int l0 = g2 * 25;
        #pragma unroll 2
        for (int l = l0; l + 1 < l0 + 25; l += 2) {
            float4 v0 = Ab[(size_t)l * 128];
            float4 v1 = Ab[(size_t)(l + 1) * 128];
            float w0 = wsm[l], w1 = wsm[l + 1];
            ax = fmaf(w0, v0.x, ax); ay = fmaf(w0, v0.y, ay);
            az = fmaf(w0, v0.z, az); aw = fmaf(w0, v0.w, aw);
            bx2 = fmaf(w1, v1.x, bx2); by2 = fmaf(w1, v1.y, by2);
            bz2 = fmaf(w1, v1.z, bz2); bw2 = fmaf(w1, v1.w, bw2);
        }
        {   // last l (25 is odd)
            int l = l0 + 24;
            float4 v0 = Ab[(size_t)l * 128];
            float w0 = wsm[l];
            ax = fmaf(w0, v0.x, ax); ay = fmaf(w0, v0.y, ay);
            az = fmaf(w0, v0.z, az); aw = fmaf(w0, v0.w, aw);
        }
        float4 r = make_float4(ax + bx2, ay + by2, az + bz2, aw + bw2);
        *(float4*)(cacc + g2 * 512 + 4 * hc) = r;
    }
    __syncthreads();
    if (t < 128) {
        float4 r0 = *(float4*)(cacc + 4 * t);
        float4 r1 = *(float4*)(cacc + 512 + 4 * t);
        float4 r2 = *(float4*)(cacc + 1024 + 4 * t);
        float4 r3 = *(float4*)(cacc + 1536 + 4 * t);
        __half2 h0 = __floats2half2_rn(r0.x + r1.x + r2.x + r3.x,
                                       r0.y + r1.y + r2.y + r3.y);
        __half2 h1 = __floats2half2_rn(r0.z + r1.z + r2.z + r3.z,
                                       r0.w + r1.w + r2.w + r3.w);
        __half2* dst = (__half2*)(minpH + (size_t)b * MINP_LD + 512 + 4 * t);
        dst[0] = h0; dst[1] = h1;
    }
}

// ---------------- K5: GRU elementwise (3 gi partials + gh w/ bias) ----------------
__global__ void gru_kernel(const float* __restrict__ giP,
                           const float* __restrict__ gh,
                           const float* __restrict__ b_ih,
                           const float* __restrict__ h0,
                           __half* __restrict__ minpH,
                           float* __restrict__ out0,
                           float* __restrict__ out1)
{
    int i = blockIdx.x * blockDim.x + threadIdx.x;  // 512*512
    int b = i >> 9, h = i & 511;
    size_t o = (size_t)b * 1536;
    const float* g0 = giP + o;
    const float* g1 = giP + 786432 + o;
    const float* g2 = giP + 1572864 + o;
    const float* q = gh + o;
    float ir = g0[h] + g1[h] + g2[h] + b_ih[h];
    float iz = g0[512 + h] + g1[512 + h] + g2[512 + h] + b_ih[512 + h];
    float in_ = g0[1024 + h] + g1[1024 + h] + g2[1024 + h] + b_ih[1024 + h];
    float hr = q[h];
    float hz = q[512 + h];
    float hn = q[1024 + h];
    float r = 1.f / (1.f + __expf(-(ir + hr)));
    float z = 1.f / (1.f + __expf(-(iz + hz)));
    float n = tanhf(in_ + r * hn);
    float hnew = (1.f - z) * n + z * h0[i];
    minpH[(size_t)b * MINP_LD + h] = __float2half_rn(hnew);
    out0[i] = hnew;
    out1[i] = hnew;
}

// ---------------- fused combine (et: 8 parts | z1: 4 parts + tanh), fp16 out -------
__global__ void combine2(const float* __restrict__ pa, const float* __restrict__ ba,
                         __half* __restrict__ oa,
                         const float* __restrict__ pz, const float* __restrict__ bz,
                         __half* __restrict__ oz)
{
    int blk = blockIdx.x;
    if (blk < 1024) {
        int i = blk * 256 + threadIdx.x;
        float v = ba[i & 511];
        #pragma unroll
        for (int j = 0; j < 8; j++) v += pa[i + (size_t)j * 262144];
        oa[i] = __float2half_rn(v);
    } else {
        int i = (blk - 1024) * 256 + threadIdx.x;
        float v = bz[i & 1023];
        #pragma unroll
        for (int j = 0; j < 4; j++) v += pz[i + (size_t)j * 524288];
        oz[i] = __float2half_rn(tanhf(v));
    }
}

// ---------------- K6: olog combine + z2/z_t + softmax + log -> p_t ----------------
__global__ void final_kernel(const float* __restrict__ ologP,
                             const float* __restrict__ out_b,
                             const float* __restrict__ z2P,
                             const float* __restrict__ zt_b2,
                             const float* __restrict__ zt_W3,
                             const float* __restrict__ zt_b3,
                             const float* __restrict__ attnw,
                             float* __restrict__ pout)
{
    __shared__ float buf[OO];
    __shared__ float sred[16];
    __shared__ float sbc;
    int b = blockIdx.x, t = threadIdx.x;  // 512 threads

    size_t o = (size_t)b * HH + t;
    float zv = z2P[o] + z2P[262144 + o] + z2P[524288 + o] + z2P[786432 + o] + zt_b2[t];
    zv = tanhf(zv);
    float s = zv * zt_W3[t];
    s = warpReduceSum(s);
    if ((t & 31) == 0) sred[t >> 5] = s;
    __syncthreads();
    if (t == 0) {
        float tot = 0.f;
        for (int w = 0; w < 16; w++) tot += sred[w];
        sbc = 1.f / (1.f + __expf(-(tot + zt_b3[0])));
    }
    __syncthreads();
    float zt = sbc;

    const float* ob0 = ologP + (size_t)b * OO;
    const float* ob1 = ob0 + (size_t)BB * OO;
    float mx = -1e30f;
    for (int j = t; j < OO; j += 512) {
        float v = ob0[j] + ob1[j] + out_b[j];
        buf[j] = v;
        mx = fmaxf(mx, v);
    }
    mx = warpReduceMax(mx);
    __syncthreads();
    if ((t & 31) == 0) sred[t >> 5] = mx;
    __syncthreads();
    if (t == 0) {
        float m2 = sred[0];
        for (int w = 1; w < 16; w++) m2 = fmaxf(m2, sred[w]);
        sbc = m2;
    }
    __syncthreads();
    mx = sbc;

    float se = 0.f;
    for (int j = t; j < OO; j += 512) {
        float e = __expf(buf[j] - mx);
        buf[j] = e;
        se += e;
    }
    se = warpReduceSum(se);
    __syncthreads();
    if ((t & 31) == 0) sred[t >> 5] = se;
    __syncthreads();
    if (t == 0) {
        float tot = 0.f;
        for (int w = 0; w < 16; w++) tot += sred[w];
        sbc = tot;
    }
    __syncthreads();
    float cc = zt / sbc;

    float* pb = pout + (size_t)b * (OO + LCC);
    for (int j = t; j < OO; j += 512)
        pb[j] = __logf(buf[j] * cc + 1e-20f);
    float omz = 1.f - zt;
    for (int l = t; l < LCC; l += 512)
        pb[OO + l] = __logf(attnw[(size_t)b * LCC + l] * omz + 1e-20f);
}

// ---------------- launch ----------------
static GDesc mkdesc(const void* A, int lda, const void* B, int ldb,
                    const float* bias, float* C, int ldc,
                    int M, int N, int K, int KC, long zstride, int zcount)
{
    GDesc d;
    d.A = A; d.B = B; d.bias = bias; d.C = C;
    d.lda = lda; d.ldb = ldb; d.ldc = ldc;
    d.N = N; d.K = K; d.KC = KC; d.zstride = zstride;
    d.ntiles = (N + 127) / 128;
    d.ctasPerZ = (M / 128) * d.ntiles;
    d.nCtas = d.ctasPerZ * zcount;
    return d;
}

extern "C" void kernel_launch(void* const* d_in, const int* in_sizes, int n_in,
                              void* d_out, int out_size)
{
    const int*   input   = (const int*)d_in[0];
    const int*   input_d = (const int*)d_in[1];
    const float* hidden  = (const float*)d_in[2];
    const float* annot   = (const float*)d_in[3];
    const float* ans     = (const float*)d_in[4];
    const float* emb_w   = (const float*)d_in[5];
    const float* emb_d_w = (const float*)d_in[6];
    const float* attn_W  = (const float*)d_in[7];
    const float* attn_b  = (const float*)d_in[8];
    const float* W_ih    = (const float*)d_in[9];
    const float* W_hh    = (const float*)d_in[10];
    const float* b_ih    = (const float*)d_in[11];
    const float* b_hh    = (const float*)d_in[12];
    const float* mlp_W   = (const float*)d_in[13];
    const float* mlp_b   = (const float*)d_in[14];
    const float* out_W   = (const float*)d_in[15];
    const float* out_b   = (const float*)d_in[16];
    const float* zt_W1   = (const float*)d_in[17];
    const float* zt_b1   = (const float*)d_in[18];
    const float* zt_W2   = (const float*)d_in[19];
    const float* zt_b2   = (const float*)d_in[20];
    const float* zt_W3   = (const float*)d_in[21];
    const float* zt_b3   = (const float*)d_in[22];
    float* out = (float*)d_out;

    float* f32 = nullptr;  __half* f16 = nullptr;
    cudaGetSymbolAddress((void**)&f32, g_f32);
    cudaGetSymbolAddress((void**)&f16, g_f16);

    float* part   = f32 + OFF_PART;
    float* attnw  = f32 + OFF_ATTNW;
    float* giP    = f32 + OFF_GIP;
    float* gh     = f32 + OFF_GH;
    float* etP    = f32 + OFF_ETP;
    float* ologP  = f32 + OFF_OLOGP;
    float* z1P    = f32 + OFF_Z1P;
    float* z2P    = f32 + OFF_Z2P;
    float* aheadF = f32 + OFF_AHEAD;

    __half* WihH  = f16 + HOFF_WIH;
    __half* mlpWH = f16 + HOFF_MLPW;
    __half* outWH = f16 + HOFF_OUTW;
    __half* z1WH  = f16 + HOFF_Z1W;
    __half* z2WH  = f16 + HOFF_Z2W;
    __half* minpH = f16 + HOFF_MINP;
    __half* etH   = f16 + HOFF_ET;
    __half* z1H   = f16 + HOFF_Z1;

    cudaFuncSetAttribute(tmma3f, cudaFuncAttributeMaxDynamicSharedMemorySize, TMMA_SMEM);
    cudaFuncSetAttribute(tmma2h, cudaFuncAttributeMaxDynamicSharedMemorySize, TMMA_SMEM);

    // 0. convert only the reused weights to fp16
    ConvSegs cs;
    const float* srcs[5] = {W_ih, mlp_W, out_W, zt_W1, zt_W2};
    __half* dsts[5] = {WihH, mlpWH, outWH, z1WH, z2WH};
    int slds[5] = {1324, 1836, 512, 1836, 1024};
    int Ks[5]   = {1324, 1836, 512, 1836, 1024};
    int Kps[5]  = {1328, 1840, 512, 1840, 1024};
    long rows[5] = {1536, 512, 2004, 1024, 512};
    long acc = 0;
    for (int i = 0; i < 5; i++) {
        cs.src[i] = srcs[i]; cs.dst[i] = dsts[i];
        cs.srcld[i] = slds[i]; cs.K[i] = Ks[i]; cs.Kp[i] = Kps[i];
        cs.start[i] = acc;
        acc += rows[i] * Kps[i];
    }
    cs.start[5] = acc;
    conv_kernel<<<2048, 256>>>(cs);

    // 1. embedding + staging
    embed_kernel<<<BB, 128>>>(input, input_d, hidden, ans, emb_w, emb_d_w, aheadF, minpH);

    // 2. tf32 triple: attn-annot (z=64) + attn-head (z=4) + gh (bias fused)
    GDesc dAA = mkdesc(annot, ANNOT_K, attn_W + AHEAD_K, 52524, nullptr,
                       part, NSPLIT * LCC, BB, LCC, ANNOT_K, 800, LCC, 64);
    GDesc dAH = mkdesc(aheadF, AHEAD_K, attn_W, 52524, nullptr,
                       part + 64 * LCC, NSPLIT * LCC, BB, LCC, AHEAD_K, 332, LCC, 4);
    GDesc dGH = mkdesc(hidden, HH, W_hh, HH, b_hh,
                       gh, 1536, BB, 1536, HH, HH, 0, 1);
    tmma3f<<<dAA.nCtas + dAH.nCtas + dGH.nCtas, 256, TMMA_SMEM>>>(dAA, dAH, dGH);

    // 3. finalize + fused c_t (reads fp32 annot)
    attn_finalize_ct<<<BB, 512>>>(part, attn_b, annot, attnw, minpH);

    // 4. gi (fp16, z=3), then GRU elementwise
    GDesc dGI = mkdesc(minpH + 512, MINP_LD, WihH, WIH_LD, nullptr,
                       giP, 1536, BB, 1536, WIH_LD, 448, 786432, 3);
    tmma2h<<<dGI.nCtas, 256, TMMA_SMEM>>>(dGI, dGI);
    gru_kernel<<<1024, 256>>>(giP, gh, b_ih, hidden, minpH, out, out + BB * HH);

    // 5. mlp + z1 fused, then fused combine
    GDesc dML = mkdesc(minpH, MINP_LD, mlpWH, MINP_LD, nullptr,
                       etP, HH, BB, HH, MINP_LD, 232, 262144, 8);
    GDesc dZ1 = mkdesc(minpH, MINP_LD, z1WH, MINP_LD, nullptr,
                       z1P, 1024, BB, 1024, MINP_LD, 464, 524288, 4);
    tmma2h<<<dML.nCtas + dZ1.nCtas, 256, TMMA_SMEM>>>(dML, dZ1);
    combine2<<<3072, 256>>>(etP, mlp_b, etH, z1P, zt_b1, z1H);

    // 6. output head (z=2, bias deferred) + z2 fused
    GDesc dOU = mkdesc(etH, HH, outWH, HH, nullptr,
                       ologP, OO, BB, OO, HH, 256, (long)BB * OO, 2);
    GDesc dZ2 = mkdesc(z1H, 1024, z2WH, 1024, nullptr,
                       z2P, HH, BB, HH, 1024, 256, 262144, 4);
    tmma2h<<<dOU.nCtas + dZ2.nCtas, 256, TMMA_SMEM>>>(dOU, dZ2);

    // 7. final: olog combine + z_t + softmax/log + p_t
    final_kernel<<<BB, 512>>>(ologP, out_b, z2P, zt_b2, zt_W3, zt_b3, attnw,
                              out + 2 * BB * HH);
}

// round 8
// speedup vs baseline: 6.5003x; 1.0288x over previous
#include <cuda_runtime.h>
#include <cuda_fp16.h>
#include <cstdint>
#include <math.h>

// ---------------- problem constants ----------------
#define BB 512
#define HH 512
#define EE 300
#define LCC 100
#define OO 2004
#define ANNOT_K 51200
#define NSPLIT 68          // 64 annot + 4 head splits
#define AHEAD_K 1324
#define MINP_LD 1840       // fp16 minp row: [h_new|c_t|ans|emb|pad4]
#define WIH_LD  1328       // 1324 padded

// ---------------- fp32 scratch ----------------
#define OFF_PART   0UL                   // 512*6800
#define OFF_ATTNW  3481600UL             // 512*100
#define OFF_GIP    3532800UL             // 3*512*1536
#define OFF_GH     5892096UL             // 512*1536
#define OFF_ETP    6678528UL             // 8*512*512
#define OFF_OLOGP  8775680UL             // 2*512*2004
#define OFF_Z1P    10827776UL            // 4*512*1024
#define OFF_Z2P    12924928UL            // 4*512*512
#define OFF_AHEAD  13973504UL            // 512*1324
#define F32_TOTAL  14651392UL

// ---------------- fp16 scratch ----------------
#define HOFF_ANNOT 0UL                   // 512*51200 (GEMM side-output)
#define HOFF_WIH   26214400UL            // 1536*1328
#define HOFF_MLPW  28254208UL            // 512*1840
#define HOFF_OUTW  29196288UL            // 2004*512
#define HOFF_Z1W   30222336UL            // 1024*1840
#define HOFF_Z2W   32106496UL            // 512*1024
#define HOFF_MINP  32630784UL            // 512*1840
#define HOFF_ET    33572864UL            // 512*512
#define HOFF_Z1    33835008UL            // 512*1024
#define F16_TOTAL  34359296UL

__device__ float g_f32[F32_TOTAL];
__device__ __align__(16) __half g_f16[F16_TOTAL];

// ---------------- low-level helpers ----------------
__device__ __forceinline__ uint32_t smem_u32(const void* p) {
    uint32_t a;
    asm("{ .reg .u64 t; cvta.to.shared.u64 t, %1; cvt.u32.u64 %0, t; }"
        : "=r"(a) : "l"(p));
    return a;
}
__device__ __forceinline__ void cpasync16(uint32_t dst, const void* src, int sz) {
    asm volatile("cp.async.cg.shared.global [%0], [%1], 16, %2;"
                 :: "r"(dst), "l"(src), "r"(sz) : "memory");
}
#define CP_COMMIT() asm volatile("cp.async.commit_group;" ::: "memory")
#define CP_WAIT1()  asm volatile("cp.async.wait_group 1;" ::: "memory")
#define LDSM4(r0, r1, r2, r3, addr) \
    asm volatile("ldmatrix.sync.aligned.m8n8.x4.shared.b16 {%0,%1,%2,%3}, [%4];" \
        : "=r"(r0), "=r"(r1), "=r"(r2), "=r"(r3) : "r"(addr))
__device__ __forceinline__ void mma_f16(float* c, const uint32_t* a, const uint32_t* b) {
    asm volatile(
        "mma.sync.aligned.m16n8k16.row.col.f32.f16.f16.f32 "
        "{%0,%1,%2,%3}, {%4,%5,%6,%7}, {%8,%9}, {%0,%1,%2,%3};"
        : "+f"(c[0]), "+f"(c[1]), "+f"(c[2]), "+f"(c[3])
        : "r"(a[0]), "r"(a[1]), "r"(a[2]), "r"(a[3]), "r"(b[0]), "r"(b[1]));
}
__device__ __forceinline__ void mma_tf32(float* c, const uint32_t* a, const uint32_t* b) {
    asm volatile(
        "mma.sync.aligned.m16n8k8.row.col.f32.tf32.tf32.f32 "
        "{%0,%1,%2,%3}, {%4,%5,%6,%7}, {%8,%9}, {%0,%1,%2,%3};"
        : "+f"(c[0]), "+f"(c[1]), "+f"(c[2]), "+f"(c[3])
        : "r"(a[0]), "r"(a[1]), "r"(a[2]), "r"(a[3]), "r"(b[0]), "r"(b[1]));
}
__device__ __forceinline__ float warpReduceSum(float v) {
    #pragma unroll
    for (int o = 16; o > 0; o >>= 1) v += __shfl_xor_sync(0xffffffffu, v, o);
    return v;
}
__device__ __forceinline__ float warpReduceMax(float v) {
    #pragma unroll
    for (int o = 16; o > 0; o >>= 1) v = fmaxf(v, __shfl_xor_sync(0xffffffffu, v, o));
    return v;
}

// ---------------- generic GEMM descriptor ----------------
struct GDesc {
    const void* A; const void* B; const float* bias; float* C;
    __half* sideout;      // optional fp16 copy of A (tf32 path only)
    int lda, ldb, ldc, N, K, KC;
    long zstride;
    int ntiles, ctasPerZ, nCtas;
};
#define TMMA_SMEM 98304

// ================= tf32 GEMM (fp32 inputs): C = A(M,K) @ B(N,K)^T =================
// BM=128, BN=128, BK=32 floats (128B rows, XOR-8 16B swizzle), 8 warps (2m x 4n),
// warp tile 64x32, 3-stage cp.async. Three fused descriptors. Optional fp16
// side-output of the A tile (each A element touched by exactly one CTA in split-K).
__device__ __forceinline__ void tmma_issue_f(
    uint32_t smbase, int p, int kk, int kend,
    const float* A, int lda, const float* B, int ldb,
    int m0, int n0, int N, int lr, int c16)
{
    const int kc = kk + (c16 << 2);
    const bool kok = (kc + 4 <= kend);
    const int szk = kok ? 16 : 0;
    #pragma unroll
    for (int i = 0; i < 4; i++) {
        int row = lr + (i << 5);
        const float* src = kok ? (A + (size_t)(m0 + row) * lda + kc) : A;
        uint32_t dst = smbase + p * 32768 + row * 128 + ((c16 ^ (row & 7)) << 4);
        cpasync16(dst, src, szk);
    }
    #pragma unroll
    for (int i = 0; i < 4; i++) {
        int row = lr + (i << 5);
        int n = n0 + row;
        bool ok = kok && (n < N);
        int sz = ok ? 16 : 0;
        const float* src = ok ? (B + (size_t)n * ldb + kc) : B;
        uint32_t dst = smbase + p * 32768 + 16384 + row * 128 + ((c16 ^ (row & 7)) << 4);
        cpasync16(dst, src, sz);
    }
    CP_COMMIT();
}

__global__ void __launch_bounds__(256, 2) tmma3f(GDesc d0, GDesc d1, GDesc d2)
{
    extern __shared__ __align__(1024) uint32_t sm[];
    const int tid = threadIdx.x;
    const int lane = tid & 31, wid = tid >> 5;
    const int wm = wid & 1, wn = wid >> 1;
    const int gid = lane >> 2, tg = lane & 3;

    int bx = blockIdx.x;
    const GDesc& d = (bx < d0.nCtas) ? d0 : ((bx < d0.nCtas + d1.nCtas) ? d1 : d2);
    if (bx >= d0.nCtas) bx -= d0.nCtas;
    if (&d == &d2) bx -= d1.nCtas;
    const int z = bx / d.ctasPerZ;
    const int r = bx % d.ctasPerZ;
    const int m0 = (r / d.ntiles) << 7;
    const int n0 = (r % d.ntiles) << 7;
    const int N = d.N, lda = d.lda, ldb = d.ldb, ldc = d.ldc;
    const float* A = (const float*)d.A;
    const float* B = (const float*)d.B;
    const int kstart = z * d.KC;
    int kend = kstart + d.KC; if (kend > d.K) kend = d.K;
    const int nb = (kend - kstart + 31) >> 5;

    const uint32_t smbase = smem_u32(sm);
    const int lr = tid >> 3, c16 = tid & 7;

    const int ahi = (lane >> 4) & 1;
    const int bhi = (lane >> 3) & 1;
    uint32_t aoff[4]; int asw[4];
    #pragma unroll
    for (int mt = 0; mt < 4; mt++) {
        int rr = wm * 64 + mt * 16 + (lane & 7) + (lane & 8);
        aoff[mt] = rr * 128;
        asw[mt] = rr & 7;
    }
    uint32_t boff[2]; int bsw[2];
    #pragma unroll
    for (int nn = 0; nn < 2; nn++) {
        int rr = wn * 32 + nn * 16 + (lane & 7) + ((lane & 16) >> 1);
        boff[nn] = 16384 + rr * 128;
        bsw[nn] = rr & 7;
    }

    float c[4][4][4];
    #pragma unroll
    for (int i = 0; i < 4; i++)
        #pragma unroll
        for (int j = 0; j < 4; j++)
            #pragma unroll
            for (int q = 0; q < 4; q++) c[i][j][q] = 0.f;

    // side-output addressing: thread covers row sr, 16 cols at chunk base scb
    const int sr = tid >> 1;
    const int scb = (tid & 1) * 4;          // smem 16B-chunk base (0 or 4)
    __half* so = d.sideout;

    tmma_issue_f(smbase, 0, kstart, kend, A, lda, B, ldb, m0, n0, N, lr, c16);
    if (nb > 1)
        tmma_issue_f(smbase, 1, kstart + 32, kend, A, lda, B, ldb, m0, n0, N, lr, c16);
    else
        CP_COMMIT();

    for (int kb = 0; kb < nb; kb++) {
        CP_WAIT1();
        __syncthreads();
        const uint32_t sp = smbase + (kb % 3) * 32768;
        #pragma unroll
        for (int ks = 0; ks < 4; ks++) {
            uint32_t af[4][4], bf[4][2];
            #pragma unroll
            for (int mt = 0; mt < 4; mt++) {
                uint32_t ad = sp + aoff[mt] + ((((ks << 1) + ahi) ^ asw[mt]) << 4);
                LDSM4(af[mt][0], af[mt][1], af[mt][2], af[mt][3], ad);
            }
            #pragma unroll
            for (int nn = 0; nn < 2; nn++) {
                uint32_t r0, r1, r2, r3;
                uint32_t bd = sp + boff[nn] + ((((ks << 1) + bhi) ^ bsw[nn]) << 4);
                LDSM4(r0, r1, r2, r3, bd);
                bf[nn * 2][0] = r0; bf[nn * 2][1] = r1;
                bf[nn * 2 + 1][0] = r2; bf[nn * 2 + 1][1] = r3;
            }
            #pragma unroll
            for (int mt = 0; mt < 4; mt++)
                #pragma unroll
                for (int nt = 0; nt < 4; nt++)
                    mma_tf32(c[mt][nt], af[mt], bf[nt]);
        }
        // fp16 side-output of this A tile (fresh in smem, guarded by sync above)
        if (so) {
            const char* base = (const char*)sm + (size_t)(kb % 3) * 32768 + sr * 128;
            __half2 hb[8];
            #pragma unroll
            for (int j = 0; j < 4; j++) {
                float4 v = *(const float4*)(base + (((scb + j) ^ (sr & 7)) << 4));
                hb[2 * j]     = __floats2half2_rn(v.x, v.y);
                hb[2 * j + 1] = __floats2half2_rn(v.z, v.w);
            }
            __half* dstp = so + (size_t)(m0 + sr) * lda + (kstart + kb * 32 + scb * 4);
            const uint4* u = (const uint4*)hb;
            *(uint4*)dstp = u[0];
            *(uint4*)(dstp + 8) = u[1];
        }
        const int nk = kb + 2;
        if (nk < nb)
            tmma_issue_f(smbase, nk % 3, kstart + nk * 32, kend,
                         A, lda, B, ldb, m0, n0, N, lr, c16);
        else
            CP_COMMIT();
    }

    const float* bias = d.bias;
    float* Cz = d.C + (size_t)z * d.zstride;
    #pragma unroll
    for (int mt = 0; mt < 4; mt++) {
        int r0 = m0 + wm * 64 + mt * 16 + gid;
        #pragma unroll
        for (int nt = 0; nt < 4; nt++) {
            int cc = n0 + wn * 32 + nt * 8 + 2 * tg;
            float* p0 = Cz + (size_t)r0 * ldc + cc;
            float* p1 = p0 + 8 * ldc;
            if (cc < N) {
                float bb = bias ? bias[cc] : 0.f;
                p0[0] = c[mt][nt][0] + bb;
                p1[0] = c[mt][nt][2] + bb;
            }
            if (cc + 1 < N) {
                float bb = bias ? bias[cc + 1] : 0.f;
                p0[1] = c[mt][nt][1] + bb;
                p1[1] = c[mt][nt][3] + bb;
            }
        }
    }
}

// ================= fp16 GEMM: C = A(M,K) @ B(N,K)^T, BK=64 halfs ================
__device__ __forceinline__ void tmma_issue_h(
    uint32_t smbase, int p, int kk, int kend,
    const __half* A, int lda, const __half* B, int ldb,
    int m0, int n0, int N, int lr, int c16)
{
    const int kc = kk + (c16 << 3);
    const bool kok = (kc + 8 <= kend);
    const int szk = kok ? 16 : 0;
    #pragma unroll
    for (int i = 0; i < 4; i++) {
        int row = lr + (i << 5);
        const __half* src = kok ? (A + (size_t)(m0 + row) * lda + kc) : A;
        uint32_t dst = smbase + p * 32768 + row * 128 + ((c16 ^ (row & 7)) << 4);
        cpasync16(dst, src, szk);
    }
    #pragma unroll
    for (int i = 0; i < 4; i++) {
        int row = lr + (i << 5);
        int n = n0 + row;
        bool ok = kok && (n < N);
        int sz = ok ? 16 : 0;
        const __half* src = ok ? (B + (size_t)n * ldb + kc) : B;
        uint32_t dst = smbase + p * 32768 + 16384 + row * 128 + ((c16 ^ (row & 7)) << 4);
        cpasync16(dst, src, sz);
    }
    CP_COMMIT();
}

__global__ void __launch_bounds__(256, 2) tmma2h(GDesc d0, GDesc d1)
{
    extern __shared__ __align__(1024) uint32_t sm[];
    const int tid = threadIdx.x;
    const int lane = tid & 31, wid = tid >> 5;
    const int wm = wid & 1, wn = wid >> 1;
    const int gid = lane >> 2, tg = lane & 3;

    int bx = blockIdx.x;
    const GDesc& d = (bx < d0.nCtas) ? d0 : d1;
    if (bx >= d0.nCtas) bx -= d0.nCtas;
    const int z = bx / d.ctasPerZ;
    const int r = bx % d.ctasPerZ;
    const int m0 = (r / d.ntiles) << 7;
    const int n0 = (r % d.ntiles) << 7;
    const int N = d.N, lda = d.lda, ldb = d.ldb, ldc = d.ldc;
    const __half* A = (const __half*)d.A;
    const __half* B = (const __half*)d.B;
    const int kstart = z * d.KC;
    int kend = kstart + d.KC; if (kend > d.K) kend = d.K;
    const int nb = (kend - kstart + 63) >> 6;

    const uint32_t smbase = smem_u32(sm);
    const int lr = tid >> 3, c16 = tid & 7;

    const int ahi = lane >> 4;
    const int bhi = (lane >> 3) & 1;
    uint32_t aoff[4]; int asw[4];
    #pragma unroll
    for (int mt = 0; mt < 4; mt++) {
        int rr = wm * 64 + mt * 16 + (lane & 15);
        aoff[mt] = rr * 128;
        asw[mt] = rr & 7;
    }
    uint32_t boff[2]; int bsw[2];
    #pragma unroll
    for (int nn = 0; nn < 2; nn++) {
        int rr = wn * 32 + nn * 16 + (lane & 7) + ((lane & 16) >> 1);
        boff[nn] = 16384 + rr * 128;
        bsw[nn] = rr & 7;
    }

    float c[4][4][4];
    #pragma unroll
    for (int i = 0; i < 4; i++)
        #pragma unroll
        for (int j = 0; j < 4; j++)
            #pragma unroll
            for (int q = 0; q < 4; q++) c[i][j][q] = 0.f;

    tmma_issue_h(smbase, 0, kstart, kend, A, lda, B, ldb, m0, n0, N, lr, c16);
    if (nb > 1)
        tmma_issue_h(smbase, 1, kstart + 64, kend, A, lda, B, ldb, m0, n0, N, lr, c16);
    else
        CP_COMMIT();

    for (int kb = 0; kb < nb; kb++) {
        CP_WAIT1();
        __syncthreads();
        const uint32_t sp = smbase + (kb % 3) * 32768;
        #pragma unroll
        for (int ks = 0; ks < 4; ks++) {
            uint32_t af[4][4], bf[4][2];
            #pragma unroll
            for (int mt = 0; mt < 4; mt++) {
                uint32_t ad = sp + aoff[mt] + ((((ks << 1) + ahi) ^ asw[mt]) << 4);
                LDSM4(af[mt][0], af[mt][1], af[mt][2], af[mt][3], ad);
            }
            #pragma unroll
            for (int nn = 0; nn < 2; nn++) {
                uint32_t r0, r1, r2, r3;
                uint32_t bd = sp + boff[nn] + ((((ks << 1) + bhi) ^ bsw[nn]) << 4);
                LDSM4(r0, r1, r2, r3, bd);
                bf[nn * 2][0] = r0; bf[nn * 2][1] = r1;
                bf[nn * 2 + 1][0] = r2; bf[nn * 2 + 1][1] = r3;
            }
            #pragma unroll
            for (int mt = 0; mt < 4; mt++)
                #pragma unroll
                for (int nt = 0; nt < 4; nt++)
                    mma_f16(c[mt][nt], af[mt], bf[nt]);
        }
        const int nk = kb + 2;
        if (nk < nb)
            tmma_issue_h(smbase, nk % 3, kstart + nk * 64, kend,
                         A, lda, B, ldb, m0, n0, N, lr, c16);
        else
            CP_COMMIT();
    }

    const float* bias = d.bias;
    float* Cz = d.C + (size_t)z * d.zstride;
    #pragma unroll
    for (int mt = 0; mt < 4; mt++) {
        int r0 = m0 + wm * 64 + mt * 16 + gid;
        #pragma unroll
        for (int nt = 0; nt < 4; nt++) {
            int cc = n0 + wn * 32 + nt * 8 + 2 * tg;
            float* p0 = Cz + (size_t)r0 * ldc + cc;
            float* p1 = p0 + 8 * ldc;
            if (cc < N) {
                float bb = bias ? bias[cc] : 0.f;
                p0[0] = c[mt][nt][0] + bb;
                p1[0] = c[mt][nt][2] + bb;
            }
            if (cc + 1 < N) {
                float bb = bias ? bias[cc + 1] : 0.f;
                p0[1] = c[mt][nt][1] + bb;
                p1[1] = c[mt][nt][3] + bb;
            }
        }
    }
}

// ================= prep: weight convert (5 segs) + embedding staging =================
struct ConvSegs {
    const float* src[5];
    __half* dst[5];
    int srcld[5], K[5], Kp[5];
    long start[6];
};

__global__ void prep_kernel(ConvSegs cs,
                            const int* __restrict__ input,
                            const int* __restrict__ input_d,
                            const float* __restrict__ hidden,
                            const float* __restrict__ ans,
                            const float* __restrict__ emb_w,
                            const float* __restrict__ emb_d_w,
                            float* __restrict__ aheadF,
                            __half* __restrict__ minpH)
{
    if (blockIdx.x < BB) {
        // ---- embed role ----
        int b = blockIdx.x, t = threadIdx.x;  // 256
        int tok = input[b];
        const float* src;
        if (tok > 2003) {
            int di = tok - 2004;
            if (di > LCC - 1) di = LCC - 1;
            if (di < 0) di = 0;
            int dt = input_d[b * LCC + di];
            src = emb_d_w + (size_t)dt * EE;
        } else {
            int tv = tok < 0 ? 0 : tok;
            src = emb_w + (size_t)tv * EE;
        }
        float* ah = aheadF + (size_t)b * AHEAD_K;
        __half* mp = minpH + (size_t)b * MINP_LD;
        for (int j = t; j < EE; j += 256) {
            float e = src[j];
            ah[512 + j] = e;
            mp[1536 + j] = __float2half_rn(e);
        }
        for (int h = t; h < HH; h += 256) {
            float hv = hidden[(size_t)b * HH + h];
            float av = ans[(size_t)b * HH + h];
            ah[h] = hv;
            ah[812 + h] = av;
            mp[1024 + h] = __float2half_rn(av);
        }
        if (t < 4) mp[1836 + t] = __float2half_rn(0.f);
    } else {
        // ---- weight convert role ----
        long total = cs.start[5] >> 3;
        long stride = 2048L * 256;
        for (long gidx = (long)(blockIdx.x - BB) * 256 + threadIdx.x;
             gidx < total; gidx += stride) {
            long e = gidx << 3;
            int s = 0;
            #pragma unroll
            for (int j = 0; j < 4; j++) if (e >= cs.start[j + 1]) s = j + 1;
            long loc = e - cs.start[s];
            int Kp = cs.Kp[s];
            long row = loc / Kp;
            int col = (int)(loc - row * Kp);
            const float* src = cs.src[s] + row * (long)cs.srcld[s] + col;
            int K = cs.K[s];
            __half2 h[4];
            if (col + 8 <= K) {
                float4 v0 = *(const float4*)src;
                float4 v1 = *(const float4*)(src + 4);
                h[0] = __floats2half2_rn(v0.x, v0.y);
                h[1] = __floats2half2_rn(v0.z, v0.w);
                h[2] = __floats2half2_rn(v1.x, v1.y);
                h[3] = __floats2half2_rn(v1.z, v1.w);
            } else {
                float tt[8];
                #pragma unroll
                for (int j = 0; j < 8; j++) tt[j] = (col + j < K) ? src[j] : 0.f;
                h[0] = __floats2half2_rn(tt[0], tt[1]);
                h[1] = __floats2half2_rn(tt[2], tt[3]);
                h[2] = __floats2half2_rn(tt[4], tt[5]);
                h[3] = __floats2half2_rn(tt[6], tt[7]);
            }
            *(uint4*)(cs.dst[s] + loc) = *(uint4*)h;
        }
    }
}

// ---------------- K3: partials reduce + tanh + softmax + fused c_t (fp16 annot) ----
__global__ void attn_finalize_ct(const float* __restrict__ partial,
                                 const float* __restrict__ attn_b,
                                 const __half* __restrict__ annotH,
                                 float* __restrict__ attnw,
                                 __half* __restrict__ minpH)
{
    __shared__ float pacc[512];
    __shared__ float sred[16];
    __shared__ float wsm[128];
    __shared__ float cacc[4096];
    int b = blockIdx.x, t = threadIdx.x;  // 512

    // phase A: reduce 68 split partials
    {
        int g = t >> 7, l = t & 127;
        const float* pb = partial + (size_t)b * (NSPLIT * LCC);
        float acc = 0.f;
        if (l < LCC) {
            int s0 = g * 17;
            #pragma unroll
            for (int s = 0; s < 17; s++) acc += pb[(s0 + s) * LCC + l];
        }
        pacc[t] = acc;
    }
    __syncthreads();
    float v = -1e30f;
    if (t < LCC)
        v = tanhf(attn_b[t] + pacc[t] + pacc[128 + t] + pacc[256 + t] + pacc[384 + t]);
    float m = warpReduceMax(v);
    if ((t & 31) == 0) sred[t >> 5] = m;
    __syncthreads();
    float mm = sred[0];
    #pragma unroll
    for (int w = 1; w < 16; w++) mm = fmaxf(mm, sred[w]);
    float e = (t < LCC) ? __expf(v - mm) : 0.f;
    float ss = warpReduceSum(e);
    __syncthreads();
    if ((t & 31) == 0) sred[t >> 5] = ss;
    __syncthreads();
    float tot = 0.f;
    #pragma unroll
    for (int w = 0; w < 16; w++) tot += sred[w];
    if (t < LCC) {
        float wv = e / tot;
        attnw[(size_t)b * LCC + t] = wv;
        wsm[t] = wv;
    }
    __syncthreads();

    // phase B: c_t[h] = sum_l w[l]*annot[b,l,h], fp16 reads, 8 l-groups x 64 h-chunks
    {
        int chunk = t & 63;       // 8 halfs -> h = chunk*8
        int g2 = t >> 6;          // 0..7
        const __half* Ab = annotH + (size_t)b * ANNOT_K + chunk * 8;
        float acc8[8];
        #pragma unroll
        for (int j = 0; j < 8; j++) acc8[j] = 0.f;
        int l = g2;
        for (; l + 8 < LCC; l += 16) {
            uint4 r0 = *(const uint4*)(Ab + (size_t)l * 512);
            uint4 r1 = *(const uint4*)(Ab + (size_t)(l + 8) * 512);
            float w0 = wsm[l], w1 = wsm[l + 8];
            const __half2* h0 = (const __half2*)&r0;
            const __half2* h1 = (const __half2*)&r1;
            #pragma unroll
            for (int j = 0; j < 4; j++) {
                float2 f0 = __half22float2(h0[j]);
                float2 f1 = __half22float2(h1[j]);
                acc8[2 * j]     = fmaf(w0, f0.x, fmaf(w1, f1.x, acc8[2 * j]));
                acc8[2 * j + 1] = fmaf(w0, f0.y, fmaf(w1, f1.y, acc8[2 * j + 1]));
            }
        }
        if (l < LCC) {
            uint4 r0 = *(const uint4*)(Ab + (size_t)l * 512);
            float w0 = wsm[l];
            const __half2* h0 = (const __half2*)&r0;
            #pragma unroll
            for (int j = 0; j < 4; j++) {
                float2 f0 = __half22float2(h0[j]);
                acc8[2 * j]     = fmaf(w0, f0.x, acc8[2 * j]);
                acc8[2 * j + 1] = fmaf(w0, f0.y, acc8[2 * j + 1]);
            }
        }
        #pragma unroll
        for (int j = 0; j < 8; j++) cacc[g2 * 512 + chunk * 8 + j] = acc8[j];
    }
    __syncthreads();
    {
        float s = 0.f;
        #pragma unroll
        for (int g = 0; g < 8; g++) s += cacc[g * 512 + t];
        minpH[(size_t)b * MINP_LD + 512 + t] = __float2half_rn(s);
    }
}

// ---------------- K5: GRU elementwise (3 gi partials + gh w/ bias) ----------------
__global__ void gru_kernel(const float* __restrict__ giP,
                           const float* __restrict__ gh,
                           const float* __restrict__ b_ih,
                           const float* __restrict__ h0,
                           __half* __restrict__ minpH,
                           float* __restrict__ out0,
                           float* __restrict__ out1)
{
    int i = blockIdx.x * blockDim.x + threadIdx.x;  // 512*512
    int b = i >> 9, h = i & 511;
    size_t o = (size_t)b * 1536;
    const float* g0 = giP + o;
    const float* g1 = giP + 786432 + o;
    const float* g2 = giP + 1572864 + o;
    const float* q = gh + o;
    float ir = g0[h] + g1[h] + g2[h] + b_ih[h];
    float iz = g0[512 + h] + g1[512 + h] + g2[512 + h] + b_ih[512 + h];
    float in_ = g0[1024 + h] + g1[1024 + h] + g2[1024 + h] + b_ih[1024 + h];
    float hr = q[h];
    float hz = q[512 + h];
    float hn = q[1024 + h];
    float r = 1.f / (1.f + __expf(-(ir + hr)));
    float z = 1.f / (1.f + __expf(-(iz + hz)));
    float n = tanhf(in_ + r * hn);
    float hnew = (1.f - z) * n + z * h0[i];
    minpH[(size_t)b * MINP_LD + h] = __float2half_rn(hnew);
    out0[i] = hnew;
    out1[i] = hnew;
}

// ---------------- fused combine (et: 8 parts | z1: 4 parts + tanh), fp16 out -------
__global__ void combine2(const float* __restrict__ pa, const float* __restrict__ ba,
                         __half* __restrict__ oa,
                         const float* __restrict__ pz, const float* __restrict__ bz,
                         __half* __restrict__ oz)
{
    int blk = blockIdx.x;
    if (blk < 1024) {
        int i = blk * 256 + threadIdx.x;
        float v = ba[i & 511];
        #pragma unroll
        for (int j = 0; j < 8; j++) v += pa[i + (size_t)j * 262144];
        oa[i] = __float2half_rn(v);
    } else {
        int i = (blk - 1024) * 256 + threadIdx.x;
        float v = bz[i & 1023];
        #pragma unroll
        for (int j = 0; j < 4; j++) v += pz[i + (size_t)j * 524288];
        oz[i] = __float2half_rn(tanhf(v));
    }
}

// ---------------- K6: olog combine + z2/z_t + softmax + log -> p_t ----------------
__global__ void final_kernel(const float* __restrict__ ologP,
                             const float* __restrict__ out_b,
                             const float* __restrict__ z2P,
                             const float* __restrict__ zt_b2,
                             const float* __restrict__ zt_W3,
                             const float* __restrict__ zt_b3,
                             const float* __restrict__ attnw,
                             float* __restrict__ pout)
{
    __shared__ float buf[OO];
    __shared__ float sred[16];
    __shared__ float sbc;
    int b = blockIdx.x, t = threadIdx.x;  // 512 threads

    size_t o = (size_t)b * HH + t;
    float zv = z2P[o] + z2P[262144 + o] + z2P[524288 + o] + z2P[786432 + o] + zt_b2[t];
    zv = tanhf(zv);
    float s = zv * zt_W3[t];
    s = warpReduceSum(s);
    if ((t & 31) == 0) sred[t >> 5] = s;
    __syncthreads();
    if (t == 0) {
        float tot = 0.f;
        for (int w = 0; w < 16; w++) tot += sred[w];
        sbc = 1.f / (1.f + __expf(-(tot + zt_b3[0])));
    }
    __syncthreads();
    float zt = sbc;

    const float* ob0 = ologP + (size_t)b * OO;
    const float* ob1 = ob0 + (size_t)BB * OO;
    float mx = -1e30f;
    for (int j = t; j < OO; j += 512) {
        float v = ob0[j] + ob1[j] + out_b[j];
        buf[j] = v;
        mx = fmaxf(mx, v);
    }
    mx = warpReduceMax(mx);
    __syncthreads();
    if ((t & 31) == 0) sred[t >> 5] = mx;
    __syncthreads();
    if (t == 0) {
        float m2 = sred[0];
        for (int w = 1; w < 16; w++) m2 = fmaxf(m2, sred[w]);
        sbc = m2;
    }
    __syncthreads();
    mx = sbc;

    float se = 0.f;
    for (int j = t; j < OO; j += 512) {
        float e = __expf(buf[j] - mx);
        buf[j] = e;
        se += e;
    }
    se = warpReduceSum(se);
    __syncthreads();
    if ((t & 31) == 0) sred[t >> 5] = se;
    __syncthreads();
    if (t == 0) {
        float tot = 0.f;
        for (int w = 0; w < 16; w++) tot += sred[w];
        sbc = tot;
    }
    __syncthreads();
    float cc = zt / sbc;

    float* pb = pout + (size_t)b * (OO + LCC);
    for (int j = t; j < OO; j += 512)
        pb[j] = __logf(buf[j] * cc + 1e-20f);
    float omz = 1.f - zt;
    for (int l = t; l < LCC; l += 512)
        pb[OO + l] = __logf(attnw[(size_t)b * LCC + l] * omz + 1e-20f);
}

// ---------------- launch ----------------
static GDesc mkdesc(const void* A, int lda, const void* B, int ldb,
                    const float* bias, float* C, int ldc,
                    int M, int N, int K, int KC, long zstride, int zcount,
                    __half* sideout = nullptr)
{
    GDesc d;
    d.A = A; d.B = B; d.bias = bias; d.C = C; d.sideout = sideout;
    d.lda = lda; d.ldb = ldb; d.ldc = ldc;
    d.N = N; d.K = K; d.KC = KC; d.zstride = zstride;
    d.ntiles = (N + 127) / 128;
    d.ctasPerZ = (M / 128) * d.ntiles;
    d.nCtas = d.ctasPerZ * zcount;
    return d;
}

extern "C" void kernel_launch(void* const* d_in, const int* in_sizes, int n_in,
                              void* d_out, int out_size)
{
    const int*   input   = (const int*)d_in[0];
    const int*   input_d = (const int*)d_in[1];
    const float* hidden  = (const float*)d_in[2];
    const float* annot   = (const float*)d_in[3];
    const float* ans     = (const float*)d_in[4];
    const float* emb_w   = (const float*)d_in[5];
    const float* emb_d_w = (const float*)d_in[6];
    const float* attn_W  = (const float*)d_in[7];
    const float* attn_b  = (const float*)d_in[8];
    const float* W_ih    = (const float*)d_in[9];
    const float* W_hh    = (const float*)d_in[10];
    const float* b_ih    = (const float*)d_in[11];
    const float* b_hh    = (const float*)d_in[12];
    const float* mlp_W   = (const float*)d_in[13];
    const float* mlp_b   = (const float*)d_in[14];
    const float* out_W   = (const float*)d_in[15];
    const float* out_b   = (const float*)d_in[16];
    const float* zt_W1   = (const float*)d_in[17];
    const float* zt_b1   = (const float*)d_in[18];
    const float* zt_W2   = (const float*)d_in[19];
    const float* zt_b2   = (const float*)d_in[20];
    const float* zt_W3   = (const float*)d_in[21];
    const float* zt_b3   = (const float*)d_in[22];
    float* out = (float*)d_out;

    float* f32 = nullptr;  __half* f16 = nullptr;
    cudaGetSymbolAddress((void**)&f32, g_f32);
    cudaGetSymbolAddress((void**)&f16, g_f16);

    float* part   = f32 + OFF_PART;
    float* attnw  = f32 + OFF_ATTNW;
    float* giP    = f32 + OFF_GIP;
    float* gh     = f32 + OFF_GH;
    float* etP    = f32 + OFF_ETP;
    float* ologP  = f32 + OFF_OLOGP;
    float* z1P    = f32 + OFF_Z1P;
    float* z2P    = f32 + OFF_Z2P;
    float* aheadF = f32 + OFF_AHEAD;

    __half* annotH = f16 + HOFF_ANNOT;
    __half* WihH   = f16 + HOFF_WIH;
    __half* mlpWH  = f16 + HOFF_MLPW;
    __half* outWH  = f16 + HOFF_OUTW;
    __half* z1WH   = f16 + HOFF_Z1W;
    __half* z2WH   = f16 + HOFF_Z2W;
    __half* minpH  = f16 + HOFF_MINP;
    __half* etH    = f16 + HOFF_ET;
    __half* z1H    = f16 + HOFF_Z1;

    cudaFuncSetAttribute(tmma3f, cudaFuncAttributeMaxDynamicSharedMemorySize, TMMA_SMEM);
    cudaFuncSetAttribute(tmma2h, cudaFuncAttributeMaxDynamicSharedMemorySize, TMMA_SMEM);

    // 0. prep: weight convert + embedding staging (one launch)
    ConvSegs cs;
    const float* srcs[5] = {W_ih, mlp_W, out_W, zt_W1, zt_W2};
    __half* dsts[5] = {WihH, mlpWH, outWH, z1WH, z2WH};
    int slds[5] = {1324, 1836, 512, 1836, 1024};
    int Ks[5]   = {1324, 1836, 512, 1836, 1024};
    int Kps[5]  = {1328, 1840, 512, 1840, 1024};
    long rows[5] = {1536, 512, 2004, 1024, 512};
    long acc = 0;
    for (int i = 0; i < 5; i++) {
        cs.src[i] = srcs[i]; cs.dst[i] = dsts[i];
        cs.srcld[i] = slds[i]; cs.K[i] = Ks[i]; cs.Kp[i] = Kps[i];
        cs.start[i] = acc;
        acc += rows[i] * Kps[i];
    }
    cs.start[5] = acc;
    prep_kernel<<<BB + 2048, 256>>>(cs, input, input_d, hidden, ans,
                                    emb_w, emb_d_w, aheadF, minpH);

    // 2. tf32 triple: attn-annot (z=64, writes annotH) + attn-head (z=4) + gh
    GDesc dAA = mkdesc(annot, ANNOT_K, attn_W + AHEAD_K, 52524, nullptr,
                       part, NSPLIT * LCC, BB, LCC, ANNOT_K, 800, LCC, 64, annotH);
    GDesc dAH = mkdesc(aheadF, AHEAD_K, attn_W, 52524, nullptr,
                       part + 64 * LCC, NSPLIT * LCC, BB, LCC, AHEAD_K, 332, LCC, 4);
    GDesc dGH = mkdesc(hidden, HH, W_hh, HH, b_hh,
                       gh, 1536, BB, 1536, HH, HH, 0, 1);
    tmma3f<<<dAA.nCtas + dAH.nCtas + dGH.nCtas, 256, TMMA_SMEM>>>(dAA, dAH, dGH);

    // 3. finalize + fused c_t (reads fp16 annotH)
    attn_finalize_ct<<<BB, 512>>>(part, attn_b, annotH, attnw, minpH);

    // 4. gi (fp16, z=3), then GRU elementwise
    GDesc dGI = mkdesc(minpH + 512, MINP_LD, WihH, WIH_LD, nullptr,
                       giP, 1536, BB, 1536, WIH_LD, 448, 786432, 3);
    tmma2h<<<dGI.nCtas, 256, TMMA_SMEM>>>(dGI, dGI);
    gru_kernel<<<1024, 256>>>(giP, gh, b_ih, hidden, minpH, out, out + BB * HH);

    // 5. mlp + z1 fused, then fused combine
    GDesc dML = mkdesc(minpH, MINP_LD, mlpWH, MINP_LD, nullptr,
                       etP, HH, BB, HH, MINP_LD, 232, 262144, 8);
    GDesc dZ1 = mkdesc(minpH, MINP_LD, z1WH, MINP_LD, nullptr,
                       z1P, 1024, BB, 1024, MINP_LD, 464, 524288, 4);
    tmma2h<<<dML.nCtas + dZ1.nCtas, 256, TMMA_SMEM>>>(dML, dZ1);
    combine2<<<3072, 256>>>(etP, mlp_b, etH, z1P, zt_b1, z1H);

    // 6. output head (z=2, bias deferred) + z2 fused
    GDesc dOU = mkdesc(etH, HH, outWH, HH, nullptr,
                       ologP, OO, BB, OO, HH, 256, (long)BB * OO, 2);
    GDesc dZ2 = mkdesc(z1H, 1024, z2WH, 1024, nullptr,
                       z2P, HH, BB, HH, 1024, 256, 262144, 4);
    tmma2h<<<dOU.nCtas + dZ2.nCtas, 256, TMMA_SMEM>>>(dOU, dZ2);

    // 7. final: olog combine + z_t + softmax/log + p_t
    final_kernel<<<BB, 512>>>(ologP, out_b, z2P, zt_b2, zt_W3, zt_b3, attnw,
                              out + 2 * BB * HH);
}